// round 7
// baseline (speedup 1.0000x reference)
#include <cuda_runtime.h>
#include <cuda_bf16.h>
#include <math_constants.h>
#include <cstdint>

#define NB 8
#define NL 2048
#define ND 1024

typedef __nv_bfloat16 bf16;

// ------------------------------ scratch ------------------------------------
__device__ bf16  g_qh[NB * NL * ND],  g_ql[NB * NL * ND];
__device__ bf16  g_kh[NB * NL * ND],  g_kl[NB * NL * ND];
__device__ bf16  g_vh[NB * NL * ND],  g_vl[NB * NL * ND];
__device__ bf16  g_Wqh[ND * ND], g_Wql[ND * ND];
__device__ bf16  g_Wkh[ND * ND], g_Wkl[ND * ND];
__device__ bf16  g_Wvh[ND * ND], g_Wvl[ND * ND];
__device__ bf16  g_Woh[ND * ND], g_Wol[ND * ND];
__device__ float g_qp[NB * NL * ND];
__device__ bf16  g_qph[NB * NL * ND], g_qpl[NB * NL * ND];
__device__ bf16  g_kph[NB * NL * ND], g_kpl[NB * NL * ND];
__device__ bf16  g_vph[NB * NL * ND], g_vpl[NB * NL * ND];
__device__ bf16  g_vpth[NB * NL * ND], g_vptl[NB * NL * ND];
__device__ float g_att[(size_t)NB * NL * NL];
__device__ bf16  g_atth[(size_t)NB * NL * NL], g_attl[(size_t)NB * NL * NL];
__device__ bf16  g_aoh[NB * NL * ND], g_aol[NB * NL * ND];
__device__ float g_x[NB * NL * ND];
__device__ unsigned char g_kmask[NB * NL];
__device__ unsigned char g_qmask[NB * NL];

// ------------------------------ helpers ------------------------------------
__device__ __forceinline__ uint32_t smem_u32(const void* p) {
    uint32_t a;
    asm("{ .reg .u64 t; cvta.to.shared.u64 t, %1; cvt.u32.u64 %0, t; }"
        : "=r"(a) : "l"(p));
    return a;
}

__device__ __forceinline__ void cpasync16(uint32_t dst, const void* src) {
    asm volatile("cp.async.cg.shared.global [%0], [%1], 16;" :: "r"(dst), "l"(src));
}

__device__ __forceinline__ void ldsm4(uint32_t* r, uint32_t addr) {
    asm volatile("ldmatrix.sync.aligned.m8n8.x4.shared.b16 {%0,%1,%2,%3}, [%4];"
                 : "=r"(r[0]), "=r"(r[1]), "=r"(r[2]), "=r"(r[3]) : "r"(addr));
}

__device__ __forceinline__ void mma16816(float* d, const uint32_t* a, const uint32_t* b) {
    asm volatile(
        "mma.sync.aligned.m16n8k16.row.col.f32.bf16.bf16.f32 "
        "{%0,%1,%2,%3}, {%4,%5,%6,%7}, {%8,%9}, {%0,%1,%2,%3};"
        : "+f"(d[0]), "+f"(d[1]), "+f"(d[2]), "+f"(d[3])
        : "r"(a[0]), "r"(a[1]), "r"(a[2]), "r"(a[3]), "r"(b[0]), "r"(b[1]));
}

// ------------------------------ GEMM ---------------------------------------
// C[M,N] = alpha * (Ahi+Alo)[M,K] @ (Bhi+Blo)[N,K]^T   (3-term bf16 split)
// CTA tile 128x128, BK=32 (64B rows), 8 warps (2x4), warp tile 64x32.
// 3-stage cp.async pipeline, 32KB/stage -> 96KB smem -> 2 CTAs/SM.
#define STG_A_H 0u
#define STG_A_L 8192u
#define STG_B_H 16384u
#define STG_B_L 24576u
#define STG_BYTES 32768u
#define GEMM_SMEM (3u * STG_BYTES)
#define MAXCH 64

__device__ __forceinline__ void load_stage(
    const bf16* __restrict__ Ah, const bf16* __restrict__ Al,
    const bf16* __restrict__ Bh, const bf16* __restrict__ Bl,
    int K, long long m0, long long n0, long long kb, uint32_t sb, int tid) {
#pragma unroll
    for (int i = 0; i < 2; i++) {
        int idx = tid + i * 256;              // 0..511: 128 rows x 4 chunks
        int row = idx >> 2, ch = idx & 3;
        uint32_t sw = (uint32_t)(row * 64 + ((ch ^ (row & 3)) << 4));
        long long ga = (m0 + row) * K + kb + ch * 8;
        cpasync16(sb + STG_A_H + sw, Ah + ga);
        cpasync16(sb + STG_A_L + sw, Al + ga);
        long long gb = (n0 + row) * K + kb + ch * 8;
        cpasync16(sb + STG_B_H + sw, Bh + gb);
        cpasync16(sb + STG_B_L + sw, Bl + gb);
    }
    asm volatile("cp.async.commit_group;" ::: "memory");
}

__global__ __launch_bounds__(256, 2)
void gemm_kernel(const bf16* __restrict__ Ah, const bf16* __restrict__ Al, long long sA,
                 const bf16* __restrict__ Bh, const bf16* __restrict__ Bl, long long sB,
                 float* __restrict__ Cf, bf16* __restrict__ Ch, bf16* __restrict__ Cl,
                 long long sC,
                 const float* __restrict__ bias, const float* __restrict__ res,
                 int K, int ldC, float alpha,
                 const unsigned char* __restrict__ mM, long long mMs,
                 const unsigned char* __restrict__ mN, long long mNs,
                 const unsigned char* __restrict__ mK, long long mKs,
                 int skipM) {
    extern __shared__ char dsm[];
    const uint32_t sb0 = smem_u32(dsm);
    const int tid = threadIdx.x;
    const int lane = tid & 31, wid = tid >> 5;
    const int warp_m = wid >> 2, warp_n = wid & 3;
    const int bz = blockIdx.z;
    Ah += (long long)bz * sA;  Al += (long long)bz * sA;
    Bh += (long long)bz * sB;  Bl += (long long)bz * sB;
    const long long coff = (long long)bz * sC;
    const long long m0 = (long long)blockIdx.y * 128;
    const long long n0 = (long long)blockIdx.x * 128;

    // ---------------- mask checks (uniform across CTA) --------------------
    int biasOnly = 0;
    if (mM) {
        mM += (long long)bz * mMs;
        int v = (tid < 128) ? (int)mM[m0 + tid] : 1;
        biasOnly = __syncthreads_and(v);
        if (biasOnly && skipM) return;
    }
    if (!biasOnly && mN) {
        mN += (long long)bz * mNs;
        int v = (tid < 128) ? (int)mN[n0 + tid] : 1;
        if (__syncthreads_and(v)) return;
    }

    // ---------------- active k-chunk list (chunks of 32) -------------------
    __shared__ int s_list[MAXCH];
    __shared__ int s_cnt;
    const int nchunks = K >> 5;
    if (!biasOnly) {
        if (mK) {
            mK += (long long)bz * mKs;
            __shared__ int s_flags[MAXCH];
            if (tid < nchunks) {
                const uint4* p = (const uint4*)(mK + tid * 32);
                uint4 x0 = p[0], x1 = p[1];
                uint32_t andall = x0.x & x0.y & x0.z & x0.w
                                & x1.x & x1.y & x1.z & x1.w;
                s_flags[tid] = (andall == 0x01010101u);
            }
            __syncthreads();
            if (tid == 0) {
                int n = 0;
                for (int c = 0; c < nchunks; c++)
                    if (!s_flags[c]) s_list[n++] = c;
                s_cnt = n;
            }
            __syncthreads();
        } else {
            if (tid < nchunks) s_list[tid] = tid;
            if (tid == 0) s_cnt = nchunks;
            __syncthreads();
        }
    }

    float acc[4][4][4];
#pragma unroll
    for (int a = 0; a < 4; a++)
#pragma unroll
        for (int b = 0; b < 4; b++)
#pragma unroll
            for (int c = 0; c < 4; c++) acc[a][b][c] = 0.0f;

    // lane-invariant fragment addressing
    const int aRow = warp_m * 64 + ((lane >> 3) & 1) * 8 + (lane & 7);
    const int aSel = lane >> 4;          // 0/1 -> 8-wide k sub-chunk
    const int bRow = warp_n * 32 + (lane >> 4) * 8 + (lane & 7);
    const int bSel = (lane >> 3) & 1;

    const int cnt = biasOnly ? 0 : s_cnt;
    if (cnt > 0) {
        load_stage(Ah, Al, Bh, Bl, K, m0, n0, (long long)s_list[0] * 32, sb0, tid);
        if (cnt > 1)
            load_stage(Ah, Al, Bh, Bl, K, m0, n0, (long long)s_list[1] * 32,
                       sb0 + STG_BYTES, tid);
        for (int i = 0; i < cnt; i++) {
            const uint32_t sb = sb0 + (uint32_t)(i % 3) * STG_BYTES;
            if (i + 2 < cnt) {
                load_stage(Ah, Al, Bh, Bl, K, m0, n0, (long long)s_list[i + 2] * 32,
                           sb0 + (uint32_t)((i + 2) % 3) * STG_BYTES, tid);
                asm volatile("cp.async.wait_group 2;" ::: "memory");
            } else if (i + 1 < cnt) {
                asm volatile("cp.async.wait_group 1;" ::: "memory");
            } else {
                asm volatile("cp.async.wait_group 0;" ::: "memory");
            }
            __syncthreads();

#pragma unroll
            for (int s = 0; s < 2; s++) {
                uint32_t ah[4][4], al[4][4], bh[2][4], bl[2][4];
#pragma unroll
                for (int mt = 0; mt < 4; mt++) {
                    int r = aRow + mt * 16;
                    uint32_t a = sb + (uint32_t)(r * 64 + (((2 * s + aSel) ^ (r & 3)) << 4));
                    ldsm4(ah[mt], a + STG_A_H);
                    ldsm4(al[mt], a + STG_A_L);
                }
#pragma unroll
                for (int p = 0; p < 2; p++) {
                    int r = bRow + p * 16;
                    uint32_t a = sb + (uint32_t)(r * 64 + (((2 * s + bSel) ^ (r & 3)) << 4));
                    ldsm4(bh[p], a + STG_B_H);
                    ldsm4(bl[p], a + STG_B_L);
                }
#pragma unroll
                for (int mt = 0; mt < 4; mt++)
#pragma unroll
                    for (int nt = 0; nt < 4; nt++)
                        mma16816(acc[mt][nt], ah[mt], &bh[nt >> 1][(nt & 1) * 2]);
#pragma unroll
                for (int mt = 0; mt < 4; mt++)
#pragma unroll
                    for (int nt = 0; nt < 4; nt++)
                        mma16816(acc[mt][nt], ah[mt], &bl[nt >> 1][(nt & 1) * 2]);
#pragma unroll
                for (int mt = 0; mt < 4; mt++)
#pragma unroll
                    for (int nt = 0; nt < 4; nt++)
                        mma16816(acc[mt][nt], al[mt], &bh[nt >> 1][(nt & 1) * 2]);
            }
            __syncthreads();
        }
    }

    // ---------------- epilogue -------------------------------------------
    const int g = lane >> 2, t = lane & 3;
#pragma unroll
    for (int mt = 0; mt < 4; mt++) {
#pragma unroll
        for (int nt = 0; nt < 4; nt++) {
            float* d = acc[mt][nt];
            int row0 = (int)m0 + warp_m * 64 + mt * 16 + g;
            int col  = (int)n0 + warp_n * 32 + nt * 8 + t * 2;
            float v0 = d[0] * alpha, v1 = d[1] * alpha;
            float v2 = d[2] * alpha, v3 = d[3] * alpha;
            if (bias) {
                float b0 = bias[col], b1 = bias[col + 1];
                v0 += b0; v1 += b1; v2 += b0; v3 += b1;
            }
            long long o0 = coff + (long long)row0 * ldC + col;
            long long o1 = o0 + 8LL * ldC;
            if (res) {
                v0 += res[o0]; v1 += res[o0 + 1];
                v2 += res[o1]; v3 += res[o1 + 1];
            }
            if (Cf) {
                *(float2*)(Cf + o0) = make_float2(v0, v1);
                *(float2*)(Cf + o1) = make_float2(v2, v3);
            }
            if (Ch) {
                __nv_bfloat162 h0, h1, l0, l1;
                h0.x = __float2bfloat16(v0); h0.y = __float2bfloat16(v1);
                h1.x = __float2bfloat16(v2); h1.y = __float2bfloat16(v3);
                l0.x = __float2bfloat16(v0 - __bfloat162float(h0.x));
                l0.y = __float2bfloat16(v1 - __bfloat162float(h0.y));
                l1.x = __float2bfloat16(v2 - __bfloat162float(h1.x));
                l1.y = __float2bfloat16(v3 - __bfloat162float(h1.y));
                *(__nv_bfloat162*)(Ch + o0) = h0;
                *(__nv_bfloat162*)(Ch + o1) = h1;
                *(__nv_bfloat162*)(Cl + o0) = l0;
                *(__nv_bfloat162*)(Cl + o1) = l1;
            }
        }
    }
}

// ---------------- fused fp32 -> bf16 hi/lo split + row-zero mask ------------
__global__ __launch_bounds__(256)
void splitmask_kernel(const float* __restrict__ x, bf16* __restrict__ h,
                      bf16* __restrict__ l, unsigned char* __restrict__ m) {
    int r = blockIdx.x;
    int tid = threadIdx.x;
    float4 v = ((const float4*)(x + (long long)r * ND))[tid];

    __shared__ float red[256];
    red[tid] = (v.x + v.y) + (v.z + v.w);
    __syncthreads();
    for (int s = 128; s > 0; s >>= 1) {
        if (tid < s) red[tid] += red[tid + s];
        __syncthreads();
    }
    if (tid == 0) m[r] = (red[0] == 0.0f) ? 1 : 0;

    bf16 hh[4], ll[4];
    float vv[4] = {v.x, v.y, v.z, v.w};
#pragma unroll
    for (int j = 0; j < 4; j++) {
        hh[j] = __float2bfloat16(vv[j]);
        ll[j] = __float2bfloat16(vv[j] - __bfloat162float(hh[j]));
    }
    long long i = (long long)r * ND + tid * 4;
    *(uint2*)(h + i) = *(uint2*)hh;
    *(uint2*)(l + i) = *(uint2*)ll;
}

// ---------------- fp32 -> bf16 hi/lo split ---------------------------------
__global__ __launch_bounds__(256)
void split_kernel(const float* __restrict__ x, bf16* __restrict__ h,
                  bf16* __restrict__ l, long long n) {
    long long i = ((long long)blockIdx.x * 256 + threadIdx.x) * 4;
    if (i >= n) return;
    float4 v = *(const float4*)(x + i);
    bf16 hh[4], ll[4];
    float vv[4] = {v.x, v.y, v.z, v.w};
#pragma unroll
    for (int j = 0; j < 4; j++) {
        hh[j] = __float2bfloat16(vv[j]);
        ll[j] = __float2bfloat16(vv[j] - __bfloat162float(hh[j]));
    }
    *(uint2*)(h + i) = *(uint2*)hh;
    *(uint2*)(l + i) = *(uint2*)ll;
}

// ---------------- masked softmax + bf16 split output ------------------------
__global__ __launch_bounds__(256)
void softmax_kernel(const float* __restrict__ att,
                    bf16* __restrict__ atth, bf16* __restrict__ attl,
                    const unsigned char* __restrict__ km,
                    const unsigned char* __restrict__ qm) {
    int i = blockIdx.x;
    int b = blockIdx.y;
    int tid = threadIdx.x;
    const float* row = att + ((long long)b * NL + i) * NL;
    bf16* oh = atth + ((long long)b * NL + i) * NL;
    bf16* ol = attl + ((long long)b * NL + i) * NL;
    const unsigned char* kmb = km + b * NL;
    bool qz = qm[b * NL + i] != 0;

    if (qz) {
        uint4 z = make_uint4(0, 0, 0, 0);
        ((uint4*)oh)[tid] = z;
        ((uint4*)ol)[tid] = z;
        return;
    }

    float vals[NL / 256];
    float mx = -CUDART_INF_F;
#pragma unroll
    for (int t = 0; t < NL / 256; t++) {
        int j = tid + t * 256;
        float v = kmb[j] ? -CUDART_INF_F : row[j];
        vals[t] = v;
        mx = fmaxf(mx, v);
    }
    __shared__ float red[256];
    red[tid] = mx;
    __syncthreads();
    for (int s = 128; s > 0; s >>= 1) {
        if (tid < s) red[tid] = fmaxf(red[tid], red[tid + s]);
        __syncthreads();
    }
    mx = red[0];
    __syncthreads();

    float sum = 0.f;
#pragma unroll
    for (int t = 0; t < NL / 256; t++) {
        float e = __expf(vals[t] - mx);
        vals[t] = e;
        sum += e;
    }
    red[tid] = sum;
    __syncthreads();
    for (int s = 128; s > 0; s >>= 1) {
        if (tid < s) red[tid] += red[tid + s];
        __syncthreads();
    }
    float inv = 1.0f / red[0];
#pragma unroll
    for (int t = 0; t < NL / 256; t++) {
        int j = tid + t * 256;
        float v = vals[t] * inv;
        bf16 h = __float2bfloat16(v);
        bf16 l = __float2bfloat16(v - __bfloat162float(h));
        oh[j] = h;
        ol[j] = l;
    }
}

// ---------------- per-batch transpose of vp hi/lo ---------------------------
__global__ __launch_bounds__(256)
void transpose_kernel(const bf16* __restrict__ h, const bf16* __restrict__ l,
                      bf16* __restrict__ th, bf16* __restrict__ tl) {
    __shared__ bf16 sh[32][33], sl[32][33];
    int b = blockIdx.z;
    int n0 = blockIdx.x * 32;
    int l0 = blockIdx.y * 32;
    int tx = threadIdx.x & 31;
    int ty = threadIdx.x >> 5;
#pragma unroll
    for (int i = 0; i < 4; i++) {
        int r = ty + i * 8;
        long long src = ((long long)b * NL + l0 + r) * ND + n0 + tx;
        sh[r][tx] = h[src];
        sl[r][tx] = l[src];
    }
    __syncthreads();
#pragma unroll
    for (int i = 0; i < 4; i++) {
        int r = ty + i * 8;
        long long dst = (long long)b * ND * NL + (long long)(n0 + r) * NL + l0 + tx;
        th[dst] = sh[tx][r];
        tl[dst] = sl[tx][r];
    }
}

// ---------------- LayerNorm (no affine), row length 1024 --------------------
__global__ __launch_bounds__(256)
void layernorm_kernel(const float* __restrict__ x, float* __restrict__ out) {
    int r = blockIdx.x;
    int tid = threadIdx.x;
    const float4* xr = (const float4*)(x + (long long)r * ND);
    float4 v = xr[tid];
    __shared__ float red[256];

    red[tid] = (v.x + v.y) + (v.z + v.w);
    __syncthreads();
    for (int s = 128; s > 0; s >>= 1) {
        if (tid < s) red[tid] += red[tid + s];
        __syncthreads();
    }
    float mu = red[0] * (1.0f / ND);
    __syncthreads();

    float dx = v.x - mu, dy = v.y - mu, dz = v.z - mu, dw = v.w - mu;
    red[tid] = dx * dx + dy * dy + dz * dz + dw * dw;
    __syncthreads();
    for (int s = 128; s > 0; s >>= 1) {
        if (tid < s) red[tid] += red[tid + s];
        __syncthreads();
    }
    float inv = rsqrtf(red[0] * (1.0f / ND) + 1e-5f);

    float4 o;
    o.x = dx * inv; o.y = dy * inv; o.z = dz * inv; o.w = dw * inv;
    ((float4*)(out + (long long)r * ND))[tid] = o;
}

// ---------------- launch -----------------------------------------------------
extern "C" void kernel_launch(void* const* d_in, const int* in_sizes, int n_in,
                              void* d_out, int out_size) {
    const float* q  = (const float*)d_in[0];
    const float* k  = (const float*)d_in[1];
    const float* v  = (const float*)d_in[2];
    const float* Wq = (const float*)d_in[3];
    const float* bq = (const float*)d_in[4];
    const float* Wk = (const float*)d_in[5];
    const float* bk = (const float*)d_in[6];
    const float* Wv = (const float*)d_in[7];
    const float* bv = (const float*)d_in[8];
    const float* Wo = (const float*)d_in[9];
    const float* bo = (const float*)d_in[10];
    float* out = (float*)d_out;

    bf16 *qh, *ql, *kh, *kl, *vh, *vl;
    bf16 *Wqh, *Wql, *Wkh, *Wkl, *Wvh, *Wvl, *Woh, *Wol;
    float *qp, *att, *x;
    bf16 *qph, *qpl, *kph, *kpl, *vph, *vpl, *vpth, *vptl, *atth, *attl, *aoh, *aol;
    unsigned char *km, *qm;
    cudaGetSymbolAddress((void**)&qh,  g_qh);   cudaGetSymbolAddress((void**)&ql,  g_ql);
    cudaGetSymbolAddress((void**)&kh,  g_kh);   cudaGetSymbolAddress((void**)&kl,  g_kl);
    cudaGetSymbolAddress((void**)&vh,  g_vh);   cudaGetSymbolAddress((void**)&vl,  g_vl);
    cudaGetSymbolAddress((void**)&Wqh, g_Wqh);  cudaGetSymbolAddress((void**)&Wql, g_Wql);
    cudaGetSymbolAddress((void**)&Wkh, g_Wkh);  cudaGetSymbolAddress((void**)&Wkl, g_Wkl);
    cudaGetSymbolAddress((void**)&Wvh, g_Wvh);  cudaGetSymbolAddress((void**)&Wvl, g_Wvl);
    cudaGetSymbolAddress((void**)&Woh, g_Woh);  cudaGetSymbolAddress((void**)&Wol, g_Wol);
    cudaGetSymbolAddress((void**)&qp,  g_qp);
    cudaGetSymbolAddress((void**)&qph, g_qph);  cudaGetSymbolAddress((void**)&qpl, g_qpl);
    cudaGetSymbolAddress((void**)&kph, g_kph);  cudaGetSymbolAddress((void**)&kpl, g_kpl);
    cudaGetSymbolAddress((void**)&vph, g_vph);  cudaGetSymbolAddress((void**)&vpl, g_vpl);
    cudaGetSymbolAddress((void**)&vpth, g_vpth); cudaGetSymbolAddress((void**)&vptl, g_vptl);
    cudaGetSymbolAddress((void**)&att, g_att);
    cudaGetSymbolAddress((void**)&atth, g_atth); cudaGetSymbolAddress((void**)&attl, g_attl);
    cudaGetSymbolAddress((void**)&aoh, g_aoh);  cudaGetSymbolAddress((void**)&aol, g_aol);
    cudaGetSymbolAddress((void**)&x,   g_x);
    cudaGetSymbolAddress((void**)&km,  g_kmask); cudaGetSymbolAddress((void**)&qm, g_qmask);

    cudaFuncSetAttribute(gemm_kernel, cudaFuncAttributeMaxDynamicSharedMemorySize, GEMM_SMEM);

    const long long E  = (long long)NB * NL * ND;
    const long long EW = (long long)ND * ND;
    const int M = NB * NL;
    const long long sQK = (long long)NL * ND;
    const long long sAT = (long long)NL * NL;
    const float scale = 0.03125f;

    splitmask_kernel<<<M, 256>>>(q, qh, ql, qm);
    splitmask_kernel<<<M, 256>>>(k, kh, kl, km);
    split_kernel<<<(int)(E / 4 / 256), 256>>>(v, vh, vl, E);
    split_kernel<<<(int)(EW / 4 / 256), 256>>>(Wq, Wqh, Wql, EW);
    split_kernel<<<(int)(EW / 4 / 256), 256>>>(Wk, Wkh, Wkl, EW);
    split_kernel<<<(int)(EW / 4 / 256), 256>>>(Wv, Wvh, Wvl, EW);
    split_kernel<<<(int)(EW / 4 / 256), 256>>>(Wo, Woh, Wol, EW);

    // projections: y = x @ W^T + b   (masked rows -> bias only)
    gemm_kernel<<<dim3(ND / 128, M / 128, 1), 256, GEMM_SMEM>>>(
        qh, ql, 0, Wqh, Wql, 0, qp, qph, qpl, 0, bq, nullptr, ND, ND, 1.0f,
        qm, 0, nullptr, 0, nullptr, 0, 0);
    gemm_kernel<<<dim3(ND / 128, M / 128, 1), 256, GEMM_SMEM>>>(
        kh, kl, 0, Wkh, Wkl, 0, nullptr, kph, kpl, 0, bk, nullptr, ND, ND, 1.0f,
        km, 0, nullptr, 0, nullptr, 0, 0);
    gemm_kernel<<<dim3(ND / 128, M / 128, 1), 256, GEMM_SMEM>>>(
        vh, vl, 0, Wvh, Wvl, 0, nullptr, vph, vpl, 0, bv, nullptr, ND, ND, 1.0f,
        km, 0, nullptr, 0, nullptr, 0, 0);

    transpose_kernel<<<dim3(ND / 32, NL / 32, NB), 256>>>(vph, vpl, vpth, vptl);

    // scores: att[b] = scale * qp[b] @ kp[b]^T
    gemm_kernel<<<dim3(NL / 128, NL / 128, NB), 256, GEMM_SMEM>>>(
        qph, qpl, sQK, kph, kpl, sQK, att, nullptr, nullptr, sAT,
        nullptr, nullptr, ND, NL, scale,
        qm, NL, km, NL, nullptr, 0, 1);

    softmax_kernel<<<dim3(NL, NB), 256>>>(att, atth, attl, km, qm);

    // context: ao[b] = att[b] @ vp[b]
    gemm_kernel<<<dim3(ND / 128, NL / 128, NB), 256, GEMM_SMEM>>>(
        atth, attl, sAT, vpth, vptl, sQK, nullptr, aoh, aol, sQK,
        nullptr, nullptr, NL, ND, 1.0f,
        qm, NL, nullptr, 0, km, NL, 0);

    // output projection + bias + residual
    gemm_kernel<<<dim3(ND / 128, M / 128, 1), 256, GEMM_SMEM>>>(
        aoh, aol, 0, Woh, Wol, 0, x, nullptr, nullptr, 0, bo, qp, ND, ND, 1.0f,
        qm, 0, nullptr, 0, nullptr, 0, 0);

    layernorm_kernel<<<M, 256>>>(x, out);
}

// round 8
// speedup vs baseline: 1.4875x; 1.4875x over previous
#include <cuda_runtime.h>
#include <cuda_fp16.h>
#include <math_constants.h>
#include <cstdint>

#define NB 8
#define NL 2048
#define ND 1024

typedef __half fp16;

// ------------------------------ scratch ------------------------------------
__device__ fp16  g_qh[NB * NL * ND],  g_ql[NB * NL * ND];
__device__ fp16  g_kh[NB * NL * ND],  g_kl[NB * NL * ND];
__device__ fp16  g_vh[NB * NL * ND],  g_vl[NB * NL * ND];
__device__ fp16  g_Wqs[ND * ND], g_Wks[ND * ND], g_Wvs[ND * ND], g_Wos[ND * ND];
__device__ float g_qp[NB * NL * ND];
__device__ fp16  g_qph[NB * NL * ND], g_qpl[NB * NL * ND];
__device__ fp16  g_kps[NB * NL * ND];
__device__ fp16  g_vps[NB * NL * ND];
__device__ fp16  g_vpts[NB * NL * ND];
__device__ float g_att[(size_t)NB * NL * NL];
__device__ fp16  g_atth[(size_t)NB * NL * NL], g_attl[(size_t)NB * NL * NL];
__device__ fp16  g_aoh[NB * NL * ND], g_aol[NB * NL * ND];
__device__ float g_x[NB * NL * ND];
__device__ unsigned char g_kmask[NB * NL];
__device__ unsigned char g_qmask[NB * NL];

// ------------------------------ helpers ------------------------------------
__device__ __forceinline__ uint32_t smem_u32(const void* p) {
    uint32_t a;
    asm("{ .reg .u64 t; cvta.to.shared.u64 t, %1; cvt.u32.u64 %0, t; }"
        : "=r"(a) : "l"(p));
    return a;
}

__device__ __forceinline__ void cpasync16(uint32_t dst, const void* src) {
    asm volatile("cp.async.cg.shared.global [%0], [%1], 16;" :: "r"(dst), "l"(src));
}

__device__ __forceinline__ void ldsm4(uint32_t* r, uint32_t addr) {
    asm volatile("ldmatrix.sync.aligned.m8n8.x4.shared.b16 {%0,%1,%2,%3}, [%4];"
                 : "=r"(r[0]), "=r"(r[1]), "=r"(r[2]), "=r"(r[3]) : "r"(addr));
}

__device__ __forceinline__ void mma16816(float* d, const uint32_t* a, const uint32_t* b) {
    asm volatile(
        "mma.sync.aligned.m16n8k16.row.col.f32.f16.f16.f32 "
        "{%0,%1,%2,%3}, {%4,%5,%6,%7}, {%8,%9}, {%0,%1,%2,%3};"
        : "+f"(d[0]), "+f"(d[1]), "+f"(d[2]), "+f"(d[3])
        : "r"(a[0]), "r"(a[1]), "r"(a[2]), "r"(a[3]), "r"(b[0]), "r"(b[1]));
}

__device__ __forceinline__ void split2(float v, fp16& h, fp16& l) {
    h = __float2half_rn(v);
    l = __float2half_rn(v - __half2float(h));
}

// ------------------------------ GEMM ---------------------------------------
// C[M,N] = alpha * (Ahi+Alo)[M,K] @ B[N,K]^T   (2-term fp16 split, B single)
// CTA tile 128x128, BK=64, 8 warps (2x4), warp tile 64x32, mma m16n8k16.
// 2-stage cp.async pipeline, 48KB/stage. Mask-aware tile/chunk skipping.
#define STG_A_H 0u
#define STG_A_L 16384u
#define STG_B   32768u
#define STG_BYTES 49152u
#define GEMM_SMEM (2u * STG_BYTES)

__device__ __forceinline__ void load_stage(
    const fp16* __restrict__ Ah, const fp16* __restrict__ Al,
    const fp16* __restrict__ B,
    int K, long long m0, long long n0, long long kb, uint32_t sb, int tid) {
#pragma unroll
    for (int i = 0; i < 4; i++) {
        int idx = tid + i * 256;              // 0..1023: 128 rows x 8 chunks
        int row = idx >> 3, ch = idx & 7;
        uint32_t sw = (uint32_t)(row * 128 + ((ch ^ (row & 7)) << 4));
        long long ga = (m0 + row) * K + kb + ch * 8;
        cpasync16(sb + STG_A_H + sw, Ah + ga);
        cpasync16(sb + STG_A_L + sw, Al + ga);
        long long gb = (n0 + row) * K + kb + ch * 8;
        cpasync16(sb + STG_B + sw, B + gb);
    }
    asm volatile("cp.async.commit_group;" ::: "memory");
}

__global__ __launch_bounds__(256, 1)
void gemm_kernel(const fp16* __restrict__ Ah, const fp16* __restrict__ Al, long long sA,
                 const fp16* __restrict__ B, long long sB,
                 float* __restrict__ Cf,
                 fp16* __restrict__ Ch, fp16* __restrict__ Cl,   // split outputs
                 fp16* __restrict__ Cs,                          // single fp16 output
                 long long sC,
                 const float* __restrict__ bias, const float* __restrict__ res,
                 int K, int ldC, float alpha,
                 const unsigned char* __restrict__ mM, long long mMs,
                 const unsigned char* __restrict__ mN, long long mNs,
                 const unsigned char* __restrict__ mK, long long mKs,
                 int skipM) {
    extern __shared__ char dsm[];
    const uint32_t sb0 = smem_u32(dsm);
    const int tid = threadIdx.x;
    const int lane = tid & 31, wid = tid >> 5;
    const int warp_m = wid >> 2, warp_n = wid & 3;
    const int bz = blockIdx.z;
    Ah += (long long)bz * sA;  Al += (long long)bz * sA;
    B  += (long long)bz * sB;
    const long long coff = (long long)bz * sC;
    const long long m0 = (long long)blockIdx.y * 128;
    const long long n0 = (long long)blockIdx.x * 128;

    // ---------------- mask checks (uniform across CTA) --------------------
    int biasOnly = 0;
    if (mM) {
        mM += (long long)bz * mMs;
        int v = (tid < 128) ? (int)mM[m0 + tid] : 1;
        biasOnly = __syncthreads_and(v);
        if (biasOnly && skipM) return;
    }
    if (!biasOnly && mN) {
        mN += (long long)bz * mNs;
        int v = (tid < 128) ? (int)mN[n0 + tid] : 1;
        if (__syncthreads_and(v)) return;
    }

    // ---------------- active k-chunk list (chunks of 64) -------------------
    __shared__ int s_list[32];
    __shared__ int s_cnt;
    const int nchunks = K >> 6;
    if (!biasOnly) {
        if (mK) {
            mK += (long long)bz * mKs;
            __shared__ int s_flags[32];
            if (tid < nchunks) {
                const uint4* p = (const uint4*)(mK + tid * 64);
                uint4 x0 = p[0], x1 = p[1], x2 = p[2], x3 = p[3];
                uint32_t andall = x0.x & x0.y & x0.z & x0.w
                                & x1.x & x1.y & x1.z & x1.w
                                & x2.x & x2.y & x2.z & x2.w
                                & x3.x & x3.y & x3.z & x3.w;
                s_flags[tid] = (andall == 0x01010101u);
            }
            __syncthreads();
            if (tid == 0) {
                int n = 0;
                for (int c = 0; c < nchunks; c++)
                    if (!s_flags[c]) s_list[n++] = c;
                s_cnt = n;
            }
            __syncthreads();
        } else {
            if (tid < nchunks) s_list[tid] = tid;
            if (tid == 0) s_cnt = nchunks;
            __syncthreads();
        }
    }

    float acc[4][4][4];
#pragma unroll
    for (int a = 0; a < 4; a++)
#pragma unroll
        for (int b = 0; b < 4; b++)
#pragma unroll
            for (int c = 0; c < 4; c++) acc[a][b][c] = 0.0f;

    // lane-invariant fragment addressing
    const int aRow = warp_m * 64 + ((lane >> 3) & 1) * 8 + (lane & 7);
    const int aSel = lane >> 4;          // 0/1 -> 8-wide k sub-chunk
    const int bRow = warp_n * 32 + (lane >> 4) * 8 + (lane & 7);
    const int bSel = (lane >> 3) & 1;

    const int cnt = biasOnly ? 0 : s_cnt;
    if (cnt > 0) {
        load_stage(Ah, Al, B, K, m0, n0, (long long)s_list[0] * 64, sb0, tid);
        for (int i = 0; i < cnt; i++) {
            const uint32_t sb = sb0 + (uint32_t)(i & 1) * STG_BYTES;
            if (i + 1 < cnt) {
                load_stage(Ah, Al, B, K, m0, n0, (long long)s_list[i + 1] * 64,
                           sb0 + (uint32_t)((i + 1) & 1) * STG_BYTES, tid);
                asm volatile("cp.async.wait_group 1;" ::: "memory");
            } else {
                asm volatile("cp.async.wait_group 0;" ::: "memory");
            }
            __syncthreads();

#pragma unroll
            for (int s = 0; s < 4; s++) {
                uint32_t ah[4][4], al[4][4], bb[2][4];
#pragma unroll
                for (int mt = 0; mt < 4; mt++) {
                    int r = aRow + mt * 16;
                    uint32_t a = sb + (uint32_t)(r * 128 + (((2 * s + aSel) ^ (r & 7)) << 4));
                    ldsm4(ah[mt], a + STG_A_H);
                    ldsm4(al[mt], a + STG_A_L);
                }
#pragma unroll
                for (int p = 0; p < 2; p++) {
                    int r = bRow + p * 16;
                    uint32_t a = sb + (uint32_t)(r * 128 + (((2 * s + bSel) ^ (r & 7)) << 4));
                    ldsm4(bb[p], a + STG_B);
                }
#pragma unroll
                for (int mt = 0; mt < 4; mt++)
#pragma unroll
                    for (int nt = 0; nt < 4; nt++)
                        mma16816(acc[mt][nt], ah[mt], &bb[nt >> 1][(nt & 1) * 2]);
#pragma unroll
                for (int mt = 0; mt < 4; mt++)
#pragma unroll
                    for (int nt = 0; nt < 4; nt++)
                        mma16816(acc[mt][nt], al[mt], &bb[nt >> 1][(nt & 1) * 2]);
            }
            __syncthreads();
        }
    }

    // ---------------- epilogue -------------------------------------------
    const int g = lane >> 2, t = lane & 3;
#pragma unroll
    for (int mt = 0; mt < 4; mt++) {
#pragma unroll
        for (int nt = 0; nt < 4; nt++) {
            float* d = acc[mt][nt];
            int row0 = (int)m0 + warp_m * 64 + mt * 16 + g;
            int col  = (int)n0 + warp_n * 32 + nt * 8 + t * 2;
            float v0 = d[0] * alpha, v1 = d[1] * alpha;
            float v2 = d[2] * alpha, v3 = d[3] * alpha;
            if (bias) {
                float b0 = bias[col], b1 = bias[col + 1];
                v0 += b0; v1 += b1; v2 += b0; v3 += b1;
            }
            long long o0 = coff + (long long)row0 * ldC + col;
            long long o1 = o0 + 8LL * ldC;
            if (res) {
                v0 += res[o0]; v1 += res[o0 + 1];
                v2 += res[o1]; v3 += res[o1 + 1];
            }
            if (Cf) {
                *(float2*)(Cf + o0) = make_float2(v0, v1);
                *(float2*)(Cf + o1) = make_float2(v2, v3);
            }
            if (Ch) {
                fp16 h0, h1, h2, h3, l0, l1, l2, l3;
                split2(v0, h0, l0); split2(v1, h1, l1);
                split2(v2, h2, l2); split2(v3, h3, l3);
                *(__half2*)(Ch + o0) = __halves2half2(h0, h1);
                *(__half2*)(Ch + o1) = __halves2half2(h2, h3);
                *(__half2*)(Cl + o0) = __halves2half2(l0, l1);
                *(__half2*)(Cl + o1) = __halves2half2(l2, l3);
            }
            if (Cs) {
                *(__half2*)(Cs + o0) = __halves2half2(__float2half_rn(v0), __float2half_rn(v1));
                *(__half2*)(Cs + o1) = __halves2half2(__float2half_rn(v2), __float2half_rn(v3));
            }
        }
    }
}

// ---------------- fused fp32 -> fp16 hi/lo split + row-zero mask ------------
__global__ __launch_bounds__(256)
void splitmask_kernel(const float* __restrict__ x, fp16* __restrict__ h,
                      fp16* __restrict__ l, unsigned char* __restrict__ m) {
    int r = blockIdx.x;
    int tid = threadIdx.x;
    float4 v = ((const float4*)(x + (long long)r * ND))[tid];

    __shared__ float red[256];
    red[tid] = (v.x + v.y) + (v.z + v.w);
    __syncthreads();
    for (int s = 128; s > 0; s >>= 1) {
        if (tid < s) red[tid] += red[tid + s];
        __syncthreads();
    }
    if (tid == 0) m[r] = (red[0] == 0.0f) ? 1 : 0;

    fp16 hh[4], ll[4];
    float vv[4] = {v.x, v.y, v.z, v.w};
#pragma unroll
    for (int j = 0; j < 4; j++) split2(vv[j], hh[j], ll[j]);
    long long i = (long long)r * ND + tid * 4;
    *(uint2*)(h + i) = *(uint2*)hh;
    *(uint2*)(l + i) = *(uint2*)ll;
}

// ---------------- fp32 -> fp16 hi/lo split -----------------------------------
__global__ __launch_bounds__(256)
void split_kernel(const float* __restrict__ x, fp16* __restrict__ h,
                  fp16* __restrict__ l, long long n) {
    long long i = ((long long)blockIdx.x * 256 + threadIdx.x) * 4;
    if (i >= n) return;
    float4 v = *(const float4*)(x + i);
    fp16 hh[4], ll[4];
    float vv[4] = {v.x, v.y, v.z, v.w};
#pragma unroll
    for (int j = 0; j < 4; j++) split2(vv[j], hh[j], ll[j]);
    *(uint2*)(h + i) = *(uint2*)hh;
    *(uint2*)(l + i) = *(uint2*)ll;
}

// ---------------- fp32 -> fp16 single convert --------------------------------
__global__ __launch_bounds__(256)
void cvt_kernel(const float* __restrict__ x, fp16* __restrict__ s, long long n) {
    long long i = ((long long)blockIdx.x * 256 + threadIdx.x) * 4;
    if (i >= n) return;
    float4 v = *(const float4*)(x + i);
    fp16 ss[4] = {__float2half_rn(v.x), __float2half_rn(v.y),
                  __float2half_rn(v.z), __float2half_rn(v.w)};
    *(uint2*)(s + i) = *(uint2*)ss;
}

// ---------------- masked softmax + fp16 split output -------------------------
__global__ __launch_bounds__(256)
void softmax_kernel(const float* __restrict__ att,
                    fp16* __restrict__ atth, fp16* __restrict__ attl,
                    const unsigned char* __restrict__ km,
                    const unsigned char* __restrict__ qm) {
    int i = blockIdx.x;
    int b = blockIdx.y;
    int tid = threadIdx.x;
    const float* row = att + ((long long)b * NL + i) * NL;
    fp16* oh = atth + ((long long)b * NL + i) * NL;
    fp16* ol = attl + ((long long)b * NL + i) * NL;
    const unsigned char* kmb = km + b * NL;
    bool qz = qm[b * NL + i] != 0;

    if (qz) {
        uint4 z = make_uint4(0, 0, 0, 0);
        ((uint4*)oh)[tid] = z;
        ((uint4*)ol)[tid] = z;
        return;
    }

    float vals[NL / 256];
    float mx = -CUDART_INF_F;
#pragma unroll
    for (int t = 0; t < NL / 256; t++) {
        int j = tid + t * 256;
        float v = kmb[j] ? -CUDART_INF_F : row[j];
        vals[t] = v;
        mx = fmaxf(mx, v);
    }
    __shared__ float red[256];
    red[tid] = mx;
    __syncthreads();
    for (int s = 128; s > 0; s >>= 1) {
        if (tid < s) red[tid] = fmaxf(red[tid], red[tid + s]);
        __syncthreads();
    }
    mx = red[0];
    __syncthreads();

    float sum = 0.f;
#pragma unroll
    for (int t = 0; t < NL / 256; t++) {
        float e = __expf(vals[t] - mx);
        vals[t] = e;
        sum += e;
    }
    red[tid] = sum;
    __syncthreads();
    for (int s = 128; s > 0; s >>= 1) {
        if (tid < s) red[tid] += red[tid + s];
        __syncthreads();
    }
    float inv = 1.0f / red[0];
#pragma unroll
    for (int t = 0; t < NL / 256; t++) {
        int j = tid + t * 256;
        float v = vals[t] * inv;
        fp16 h, l;
        split2(v, h, l);
        oh[j] = h;
        ol[j] = l;
    }
}

// ---------------- per-batch transpose of vp (single fp16) --------------------
__global__ __launch_bounds__(256)
void transpose_kernel(const fp16* __restrict__ s, fp16* __restrict__ ts) {
    __shared__ fp16 sh[32][33];
    int b = blockIdx.z;
    int n0 = blockIdx.x * 32;
    int l0 = blockIdx.y * 32;
    int tx = threadIdx.x & 31;
    int ty = threadIdx.x >> 5;
#pragma unroll
    for (int i = 0; i < 4; i++) {
        int r = ty + i * 8;
        sh[r][tx] = s[((long long)b * NL + l0 + r) * ND + n0 + tx];
    }
    __syncthreads();
#pragma unroll
    for (int i = 0; i < 4; i++) {
        int r = ty + i * 8;
        ts[(long long)b * ND * NL + (long long)(n0 + r) * NL + l0 + tx] = sh[tx][r];
    }
}

// ---------------- LayerNorm (no affine), row length 1024 --------------------
__global__ __launch_bounds__(256)
void layernorm_kernel(const float* __restrict__ x, float* __restrict__ out) {
    int r = blockIdx.x;
    int tid = threadIdx.x;
    const float4* xr = (const float4*)(x + (long long)r * ND);
    float4 v = xr[tid];
    __shared__ float red[256];

    red[tid] = (v.x + v.y) + (v.z + v.w);
    __syncthreads();
    for (int s = 128; s > 0; s >>= 1) {
        if (tid < s) red[tid] += red[tid + s];
        __syncthreads();
    }
    float mu = red[0] * (1.0f / ND);
    __syncthreads();

    float dx = v.x - mu, dy = v.y - mu, dz = v.z - mu, dw = v.w - mu;
    red[tid] = dx * dx + dy * dy + dz * dz + dw * dw;
    __syncthreads();
    for (int s = 128; s > 0; s >>= 1) {
        if (tid < s) red[tid] += red[tid + s];
        __syncthreads();
    }
    float inv = rsqrtf(red[0] * (1.0f / ND) + 1e-5f);

    float4 o;
    o.x = dx * inv; o.y = dy * inv; o.z = dz * inv; o.w = dw * inv;
    ((float4*)(out + (long long)r * ND))[tid] = o;
}

// ---------------- launch -----------------------------------------------------
extern "C" void kernel_launch(void* const* d_in, const int* in_sizes, int n_in,
                              void* d_out, int out_size) {
    const float* q  = (const float*)d_in[0];
    const float* k  = (const float*)d_in[1];
    const float* v  = (const float*)d_in[2];
    const float* Wq = (const float*)d_in[3];
    const float* bq = (const float*)d_in[4];
    const float* Wk = (const float*)d_in[5];
    const float* bk = (const float*)d_in[6];
    const float* Wv = (const float*)d_in[7];
    const float* bv = (const float*)d_in[8];
    const float* Wo = (const float*)d_in[9];
    const float* bo = (const float*)d_in[10];
    float* out = (float*)d_out;

    fp16 *qh, *ql, *kh, *kl, *vh, *vl;
    fp16 *Wqs, *Wks, *Wvs, *Wos;
    float *qp, *att, *x;
    fp16 *qph, *qpl, *kps, *vps, *vpts, *atth, *attl, *aoh, *aol;
    unsigned char *km, *qm;
    cudaGetSymbolAddress((void**)&qh,  g_qh);   cudaGetSymbolAddress((void**)&ql,  g_ql);
    cudaGetSymbolAddress((void**)&kh,  g_kh);   cudaGetSymbolAddress((void**)&kl,  g_kl);
    cudaGetSymbolAddress((void**)&vh,  g_vh);   cudaGetSymbolAddress((void**)&vl,  g_vl);
    cudaGetSymbolAddress((void**)&Wqs, g_Wqs);  cudaGetSymbolAddress((void**)&Wks, g_Wks);
    cudaGetSymbolAddress((void**)&Wvs, g_Wvs);  cudaGetSymbolAddress((void**)&Wos, g_Wos);
    cudaGetSymbolAddress((void**)&qp,  g_qp);
    cudaGetSymbolAddress((void**)&qph, g_qph);  cudaGetSymbolAddress((void**)&qpl, g_qpl);
    cudaGetSymbolAddress((void**)&kps, g_kps);
    cudaGetSymbolAddress((void**)&vps, g_vps);  cudaGetSymbolAddress((void**)&vpts, g_vpts);
    cudaGetSymbolAddress((void**)&att, g_att);
    cudaGetSymbolAddress((void**)&atth, g_atth); cudaGetSymbolAddress((void**)&attl, g_attl);
    cudaGetSymbolAddress((void**)&aoh, g_aoh);  cudaGetSymbolAddress((void**)&aol, g_aol);
    cudaGetSymbolAddress((void**)&x,   g_x);
    cudaGetSymbolAddress((void**)&km,  g_kmask); cudaGetSymbolAddress((void**)&qm, g_qmask);

    cudaFuncSetAttribute(gemm_kernel, cudaFuncAttributeMaxDynamicSharedMemorySize, GEMM_SMEM);

    const long long E  = (long long)NB * NL * ND;
    const long long EW = (long long)ND * ND;
    const int M = NB * NL;
    const long long sQK = (long long)NL * ND;
    const long long sAT = (long long)NL * NL;
    const float scale = 0.03125f;

    // fused split + mask for q,k; split for v; single-fp16 convert for weights
    splitmask_kernel<<<M, 256>>>(q, qh, ql, qm);
    splitmask_kernel<<<M, 256>>>(k, kh, kl, km);
    split_kernel<<<(int)(E / 4 / 256), 256>>>(v, vh, vl, E);
    cvt_kernel<<<(int)(EW / 4 / 256), 256>>>(Wq, Wqs, EW);
    cvt_kernel<<<(int)(EW / 4 / 256), 256>>>(Wk, Wks, EW);
    cvt_kernel<<<(int)(EW / 4 / 256), 256>>>(Wv, Wvs, EW);
    cvt_kernel<<<(int)(EW / 4 / 256), 256>>>(Wo, Wos, EW);

    // projections: y = x @ W^T + b   (masked rows -> bias only)
    gemm_kernel<<<dim3(ND / 128, M / 128, 1), 256, GEMM_SMEM>>>(
        qh, ql, 0, Wqs, 0, qp, qph, qpl, nullptr, 0, bq, nullptr, ND, ND, 1.0f,
        qm, 0, nullptr, 0, nullptr, 0, 0);
    gemm_kernel<<<dim3(ND / 128, M / 128, 1), 256, GEMM_SMEM>>>(
        kh, kl, 0, Wks, 0, nullptr, nullptr, nullptr, kps, 0, bk, nullptr, ND, ND, 1.0f,
        km, 0, nullptr, 0, nullptr, 0, 0);
    gemm_kernel<<<dim3(ND / 128, M / 128, 1), 256, GEMM_SMEM>>>(
        vh, vl, 0, Wvs, 0, nullptr, nullptr, nullptr, vps, 0, bv, nullptr, ND, ND, 1.0f,
        km, 0, nullptr, 0, nullptr, 0, 0);

    // vp -> vp^T per batch
    transpose_kernel<<<dim3(ND / 32, NL / 32, NB), 256>>>(vps, vpts);

    // scores: att[b] = scale * qp[b] @ kp[b]^T  (skip all-masked q/k tiles)
    gemm_kernel<<<dim3(NL / 128, NL / 128, NB), 256, GEMM_SMEM>>>(
        qph, qpl, sQK, kps, sQK, att, nullptr, nullptr, nullptr, sAT,
        nullptr, nullptr, ND, NL, scale,
        qm, NL, km, NL, nullptr, 0, 1);

    // masked softmax + fp16 split
    softmax_kernel<<<dim3(NL, NB), 256>>>(att, atth, attl, km, qm);

    // context: ao[b] = att[b] @ vp[b]  (skip masked q tiles + masked k chunks)
    gemm_kernel<<<dim3(ND / 128, NL / 128, NB), 256, GEMM_SMEM>>>(
        atth, attl, sAT, vpts, sQK, nullptr, aoh, aol, nullptr, sQK,
        nullptr, nullptr, NL, ND, 1.0f,
        qm, NL, nullptr, 0, km, NL, 0);

    // output projection + bias + residual (projected q)
    gemm_kernel<<<dim3(ND / 128, M / 128, 1), 256, GEMM_SMEM>>>(
        aoh, aol, 0, Wos, 0, x, nullptr, nullptr, nullptr, 0, bo, qp, ND, ND, 1.0f,
        qm, 0, nullptr, 0, nullptr, 0, 0);

    // LayerNorm -> final output
    layernorm_kernel<<<M, 256>>>(x, out);
}

// round 9
// speedup vs baseline: 2.1997x; 1.4788x over previous
#include <cuda_runtime.h>
#include <cuda_fp16.h>
#include <math_constants.h>
#include <cstdint>

#define NB 8
#define NL 2048
#define ND 1024

typedef __half fp16;

// ------------------------------ scratch ------------------------------------
__device__ fp16  g_qs[NB * NL * ND], g_ks[NB * NL * ND], g_vs[NB * NL * ND];
__device__ fp16  g_Wqs[ND * ND], g_Wks[ND * ND], g_Wvs[ND * ND], g_Wos[ND * ND];
__device__ float g_qp[NB * NL * ND];
__device__ fp16  g_qps[NB * NL * ND];
__device__ fp16  g_kps[NB * NL * ND];
__device__ fp16  g_vps[NB * NL * ND];
__device__ fp16  g_vpts[NB * NL * ND];
__device__ float g_att[(size_t)NB * NL * NL];
__device__ fp16  g_atts[(size_t)NB * NL * NL];
__device__ fp16  g_aos[NB * NL * ND];
__device__ float g_x[NB * NL * ND];
__device__ unsigned char g_kmask[NB * NL];
__device__ unsigned char g_qmask[NB * NL];

// ------------------------------ helpers ------------------------------------
__device__ __forceinline__ uint32_t smem_u32(const void* p) {
    uint32_t a;
    asm("{ .reg .u64 t; cvta.to.shared.u64 t, %1; cvt.u32.u64 %0, t; }"
        : "=r"(a) : "l"(p));
    return a;
}

__device__ __forceinline__ void cpasync16(uint32_t dst, const void* src) {
    asm volatile("cp.async.cg.shared.global [%0], [%1], 16;" :: "r"(dst), "l"(src));
}

__device__ __forceinline__ void ldsm4(uint32_t* r, uint32_t addr) {
    asm volatile("ldmatrix.sync.aligned.m8n8.x4.shared.b16 {%0,%1,%2,%3}, [%4];"
                 : "=r"(r[0]), "=r"(r[1]), "=r"(r[2]), "=r"(r[3]) : "r"(addr));
}

__device__ __forceinline__ void mma16816(float* d, const uint32_t* a, const uint32_t* b) {
    asm volatile(
        "mma.sync.aligned.m16n8k16.row.col.f32.f16.f16.f32 "
        "{%0,%1,%2,%3}, {%4,%5,%6,%7}, {%8,%9}, {%0,%1,%2,%3};"
        : "+f"(d[0]), "+f"(d[1]), "+f"(d[2]), "+f"(d[3])
        : "r"(a[0]), "r"(a[1]), "r"(a[2]), "r"(a[3]), "r"(b[0]), "r"(b[1]));
}

// ------------------------------ GEMM ---------------------------------------
// C[M,N] = alpha * A[M,K] @ B[N,K]^T   (single fp16 operands, fp32 accum)
// CTA tile 128x128, BK=64, 8 warps (2x4), warp tile 64x32, mma m16n8k16.
// 2-stage cp.async pipeline, 32KB/stage. Mask-aware tile/chunk skipping.
#define STG_A   0u
#define STG_B   16384u
#define STG_BYTES 32768u
#define GEMM_SMEM (2u * STG_BYTES)

__device__ __forceinline__ void load_stage(
    const fp16* __restrict__ A, const fp16* __restrict__ B,
    int K, long long m0, long long n0, long long kb, uint32_t sb, int tid) {
#pragma unroll
    for (int i = 0; i < 4; i++) {
        int idx = tid + i * 256;              // 0..1023: 128 rows x 8 chunks
        int row = idx >> 3, ch = idx & 7;
        uint32_t sw = (uint32_t)(row * 128 + ((ch ^ (row & 7)) << 4));
        cpasync16(sb + STG_A + sw, A + (m0 + row) * K + kb + ch * 8);
        cpasync16(sb + STG_B + sw, B + (n0 + row) * K + kb + ch * 8);
    }
    asm volatile("cp.async.commit_group;" ::: "memory");
}

__global__ __launch_bounds__(256, 1)
void gemm_kernel(const fp16* __restrict__ A, long long sA,
                 const fp16* __restrict__ B, long long sB,
                 float* __restrict__ Cf, fp16* __restrict__ Cs, long long sC,
                 const float* __restrict__ bias, const float* __restrict__ res,
                 int K, int ldC, float alpha,
                 const unsigned char* __restrict__ mM, long long mMs,
                 const unsigned char* __restrict__ mN, long long mNs,
                 const unsigned char* __restrict__ mK, long long mKs,
                 int skipM) {
    extern __shared__ char dsm[];
    const uint32_t sb0 = smem_u32(dsm);
    const int tid = threadIdx.x;
    const int lane = tid & 31, wid = tid >> 5;
    const int warp_m = wid >> 2, warp_n = wid & 3;
    const int bz = blockIdx.z;
    A += (long long)bz * sA;
    B += (long long)bz * sB;
    const long long coff = (long long)bz * sC;
    const long long m0 = (long long)blockIdx.y * 128;
    const long long n0 = (long long)blockIdx.x * 128;

    // ---------------- mask checks (uniform across CTA) --------------------
    int biasOnly = 0;
    if (mM) {
        mM += (long long)bz * mMs;
        int v = (tid < 128) ? (int)mM[m0 + tid] : 1;
        biasOnly = __syncthreads_and(v);
        if (biasOnly && skipM) return;
    }
    if (!biasOnly && mN) {
        mN += (long long)bz * mNs;
        int v = (tid < 128) ? (int)mN[n0 + tid] : 1;
        if (__syncthreads_and(v)) return;
    }

    // ---------------- active k-chunk list (chunks of 64) -------------------
    __shared__ int s_list[32];
    __shared__ int s_cnt;
    const int nchunks = K >> 6;
    if (!biasOnly) {
        if (mK) {
            mK += (long long)bz * mKs;
            __shared__ int s_flags[32];
            if (tid < nchunks) {
                const uint4* p = (const uint4*)(mK + tid * 64);
                uint4 x0 = p[0], x1 = p[1], x2 = p[2], x3 = p[3];
                uint32_t andall = x0.x & x0.y & x0.z & x0.w
                                & x1.x & x1.y & x1.z & x1.w
                                & x2.x & x2.y & x2.z & x2.w
                                & x3.x & x3.y & x3.z & x3.w;
                s_flags[tid] = (andall == 0x01010101u);
            }
            __syncthreads();
            if (tid == 0) {
                int n = 0;
                for (int c = 0; c < nchunks; c++)
                    if (!s_flags[c]) s_list[n++] = c;
                s_cnt = n;
            }
            __syncthreads();
        } else {
            if (tid < nchunks) s_list[tid] = tid;
            if (tid == 0) s_cnt = nchunks;
            __syncthreads();
        }
    }

    float acc[4][4][4];
#pragma unroll
    for (int a = 0; a < 4; a++)
#pragma unroll
        for (int b = 0; b < 4; b++)
#pragma unroll
            for (int c = 0; c < 4; c++) acc[a][b][c] = 0.0f;

    // lane-invariant fragment addressing
    const int aRow = warp_m * 64 + ((lane >> 3) & 1) * 8 + (lane & 7);
    const int aSel = lane >> 4;          // 0/1 -> 8-wide k sub-chunk
    const int bRow = warp_n * 32 + (lane >> 4) * 8 + (lane & 7);
    const int bSel = (lane >> 3) & 1;

    const int cnt = biasOnly ? 0 : s_cnt;
    if (cnt > 0) {
        load_stage(A, B, K, m0, n0, (long long)s_list[0] * 64, sb0, tid);
        for (int i = 0; i < cnt; i++) {
            const uint32_t sb = sb0 + (uint32_t)(i & 1) * STG_BYTES;
            if (i + 1 < cnt) {
                load_stage(A, B, K, m0, n0, (long long)s_list[i + 1] * 64,
                           sb0 + (uint32_t)((i + 1) & 1) * STG_BYTES, tid);
                asm volatile("cp.async.wait_group 1;" ::: "memory");
            } else {
                asm volatile("cp.async.wait_group 0;" ::: "memory");
            }
            __syncthreads();

#pragma unroll
            for (int s = 0; s < 4; s++) {
                uint32_t aa[4][4], bb[2][4];
#pragma unroll
                for (int mt = 0; mt < 4; mt++) {
                    int r = aRow + mt * 16;
                    ldsm4(aa[mt], sb + STG_A +
                          (uint32_t)(r * 128 + (((2 * s + aSel) ^ (r & 7)) << 4)));
                }
#pragma unroll
                for (int p = 0; p < 2; p++) {
                    int r = bRow + p * 16;
                    ldsm4(bb[p], sb + STG_B +
                          (uint32_t)(r * 128 + (((2 * s + bSel) ^ (r & 7)) << 4)));
                }
#pragma unroll
                for (int mt = 0; mt < 4; mt++)
#pragma unroll
                    for (int nt = 0; nt < 4; nt++)
                        mma16816(acc[mt][nt], aa[mt], &bb[nt >> 1][(nt & 1) * 2]);
            }
            __syncthreads();
        }
    }

    // ---------------- epilogue -------------------------------------------
    const int g = lane >> 2, t = lane & 3;
#pragma unroll
    for (int mt = 0; mt < 4; mt++) {
#pragma unroll
        for (int nt = 0; nt < 4; nt++) {
            float* d = acc[mt][nt];
            int row0 = (int)m0 + warp_m * 64 + mt * 16 + g;
            int col  = (int)n0 + warp_n * 32 + nt * 8 + t * 2;
            float v0 = d[0] * alpha, v1 = d[1] * alpha;
            float v2 = d[2] * alpha, v3 = d[3] * alpha;
            if (bias) {
                float b0 = bias[col], b1 = bias[col + 1];
                v0 += b0; v1 += b1; v2 += b0; v3 += b1;
            }
            long long o0 = coff + (long long)row0 * ldC + col;
            long long o1 = o0 + 8LL * ldC;
            if (res) {
                v0 += res[o0]; v1 += res[o0 + 1];
                v2 += res[o1]; v3 += res[o1 + 1];
            }
            if (Cf) {
                *(float2*)(Cf + o0) = make_float2(v0, v1);
                *(float2*)(Cf + o1) = make_float2(v2, v3);
            }
            if (Cs) {
                *(__half2*)(Cs + o0) = __halves2half2(__float2half_rn(v0), __float2half_rn(v1));
                *(__half2*)(Cs + o1) = __halves2half2(__float2half_rn(v2), __float2half_rn(v3));
            }
        }
    }
}

// ---------------- fused fp32 -> fp16 convert + row-zero mask ----------------
__global__ __launch_bounds__(256)
void cvtmask_kernel(const float* __restrict__ x, fp16* __restrict__ s,
                    unsigned char* __restrict__ m) {
    int r = blockIdx.x;
    int tid = threadIdx.x;
    float4 v = ((const float4*)(x + (long long)r * ND))[tid];

    __shared__ float red[256];
    red[tid] = (v.x + v.y) + (v.z + v.w);
    __syncthreads();
    for (int st = 128; st > 0; st >>= 1) {
        if (tid < st) red[tid] += red[tid + st];
        __syncthreads();
    }
    if (tid == 0) m[r] = (red[0] == 0.0f) ? 1 : 0;

    fp16 ss[4] = {__float2half_rn(v.x), __float2half_rn(v.y),
                  __float2half_rn(v.z), __float2half_rn(v.w)};
    *(uint2*)(s + (long long)r * ND + tid * 4) = *(uint2*)ss;
}

// ---------------- fp32 -> fp16 convert ---------------------------------------
__global__ __launch_bounds__(256)
void cvt_kernel(const float* __restrict__ x, fp16* __restrict__ s, long long n) {
    long long i = ((long long)blockIdx.x * 256 + threadIdx.x) * 4;
    if (i >= n) return;
    float4 v = *(const float4*)(x + i);
    fp16 ss[4] = {__float2half_rn(v.x), __float2half_rn(v.y),
                  __float2half_rn(v.z), __float2half_rn(v.w)};
    *(uint2*)(s + i) = *(uint2*)ss;
}

// ---------------- masked softmax + fp16 output -------------------------------
__global__ __launch_bounds__(256)
void softmax_kernel(const float* __restrict__ att, fp16* __restrict__ atts,
                    const unsigned char* __restrict__ km,
                    const unsigned char* __restrict__ qm) {
    int i = blockIdx.x;
    int b = blockIdx.y;
    int tid = threadIdx.x;
    const float* row = att + ((long long)b * NL + i) * NL;
    fp16* os = atts + ((long long)b * NL + i) * NL;
    const unsigned char* kmb = km + b * NL;
    bool qz = qm[b * NL + i] != 0;

    if (qz) {   // masked q row: output exactly zero, never read scores
        ((uint4*)os)[tid] = make_uint4(0, 0, 0, 0);
        return;
    }

    float vals[NL / 256];
    float mx = -CUDART_INF_F;
#pragma unroll
    for (int t = 0; t < NL / 256; t++) {
        int j = tid + t * 256;
        float v = kmb[j] ? -CUDART_INF_F : row[j];
        vals[t] = v;
        mx = fmaxf(mx, v);
    }
    __shared__ float red[256];
    red[tid] = mx;
    __syncthreads();
    for (int s = 128; s > 0; s >>= 1) {
        if (tid < s) red[tid] = fmaxf(red[tid], red[tid + s]);
        __syncthreads();
    }
    mx = red[0];
    __syncthreads();

    float sum = 0.f;
#pragma unroll
    for (int t = 0; t < NL / 256; t++) {
        float e = __expf(vals[t] - mx);
        vals[t] = e;
        sum += e;
    }
    red[tid] = sum;
    __syncthreads();
    for (int s = 128; s > 0; s >>= 1) {
        if (tid < s) red[tid] += red[tid + s];
        __syncthreads();
    }
    float inv = 1.0f / red[0];
#pragma unroll
    for (int t = 0; t < NL / 256; t++) {
        int j = tid + t * 256;
        os[j] = __float2half_rn(vals[t] * inv);
    }
}

// ---------------- per-batch transpose of vp (single fp16) --------------------
__global__ __launch_bounds__(256)
void transpose_kernel(const fp16* __restrict__ s, fp16* __restrict__ ts) {
    __shared__ fp16 sh[32][33];
    int b = blockIdx.z;
    int n0 = blockIdx.x * 32;
    int l0 = blockIdx.y * 32;
    int tx = threadIdx.x & 31;
    int ty = threadIdx.x >> 5;
#pragma unroll
    for (int i = 0; i < 4; i++) {
        int r = ty + i * 8;
        sh[r][tx] = s[((long long)b * NL + l0 + r) * ND + n0 + tx];
    }
    __syncthreads();
#pragma unroll
    for (int i = 0; i < 4; i++) {
        int r = ty + i * 8;
        ts[(long long)b * ND * NL + (long long)(n0 + r) * NL + l0 + tx] = sh[tx][r];
    }
}

// ---------------- LayerNorm (no affine), row length 1024 --------------------
__global__ __launch_bounds__(256)
void layernorm_kernel(const float* __restrict__ x, float* __restrict__ out) {
    int r = blockIdx.x;
    int tid = threadIdx.x;
    const float4* xr = (const float4*)(x + (long long)r * ND);
    float4 v = xr[tid];
    __shared__ float red[256];

    red[tid] = (v.x + v.y) + (v.z + v.w);
    __syncthreads();
    for (int s = 128; s > 0; s >>= 1) {
        if (tid < s) red[tid] += red[tid + s];
        __syncthreads();
    }
    float mu = red[0] * (1.0f / ND);
    __syncthreads();

    float dx = v.x - mu, dy = v.y - mu, dz = v.z - mu, dw = v.w - mu;
    red[tid] = dx * dx + dy * dy + dz * dz + dw * dw;
    __syncthreads();
    for (int s = 128; s > 0; s >>= 1) {
        if (tid < s) red[tid] += red[tid + s];
        __syncthreads();
    }
    float inv = rsqrtf(red[0] * (1.0f / ND) + 1e-5f);

    float4 o;
    o.x = dx * inv; o.y = dy * inv; o.z = dz * inv; o.w = dw * inv;
    ((float4*)(out + (long long)r * ND))[tid] = o;
}

// ---------------- launch -----------------------------------------------------
extern "C" void kernel_launch(void* const* d_in, const int* in_sizes, int n_in,
                              void* d_out, int out_size) {
    const float* q  = (const float*)d_in[0];
    const float* k  = (const float*)d_in[1];
    const float* v  = (const float*)d_in[2];
    const float* Wq = (const float*)d_in[3];
    const float* bq = (const float*)d_in[4];
    const float* Wk = (const float*)d_in[5];
    const float* bk = (const float*)d_in[6];
    const float* Wv = (const float*)d_in[7];
    const float* bv = (const float*)d_in[8];
    const float* Wo = (const float*)d_in[9];
    const float* bo = (const float*)d_in[10];
    float* out = (float*)d_out;

    fp16 *qs, *ks, *vs, *Wqs, *Wks, *Wvs, *Wos;
    float *qp, *att, *x;
    fp16 *qps, *kps, *vps, *vpts, *atts, *aos;
    unsigned char *km, *qm;
    cudaGetSymbolAddress((void**)&qs,  g_qs);
    cudaGetSymbolAddress((void**)&ks,  g_ks);
    cudaGetSymbolAddress((void**)&vs,  g_vs);
    cudaGetSymbolAddress((void**)&Wqs, g_Wqs);  cudaGetSymbolAddress((void**)&Wks, g_Wks);
    cudaGetSymbolAddress((void**)&Wvs, g_Wvs);  cudaGetSymbolAddress((void**)&Wos, g_Wos);
    cudaGetSymbolAddress((void**)&qp,  g_qp);
    cudaGetSymbolAddress((void**)&qps, g_qps);
    cudaGetSymbolAddress((void**)&kps, g_kps);
    cudaGetSymbolAddress((void**)&vps, g_vps);  cudaGetSymbolAddress((void**)&vpts, g_vpts);
    cudaGetSymbolAddress((void**)&att, g_att);
    cudaGetSymbolAddress((void**)&atts, g_atts);
    cudaGetSymbolAddress((void**)&aos, g_aos);
    cudaGetSymbolAddress((void**)&x,   g_x);
    cudaGetSymbolAddress((void**)&km,  g_kmask); cudaGetSymbolAddress((void**)&qm, g_qmask);

    cudaFuncSetAttribute(gemm_kernel, cudaFuncAttributeMaxDynamicSharedMemorySize, GEMM_SMEM);

    const long long E  = (long long)NB * NL * ND;
    const long long EW = (long long)ND * ND;
    const int M = NB * NL;
    const long long sQK = (long long)NL * ND;
    const long long sAT = (long long)NL * NL;
    const float scale = 0.03125f;

    // fused convert + mask for q,k; plain converts for v and weights
    cvtmask_kernel<<<M, 256>>>(q, qs, qm);
    cvtmask_kernel<<<M, 256>>>(k, ks, km);
    cvt_kernel<<<(int)(E / 4 / 256), 256>>>(v, vs, E);
    cvt_kernel<<<(int)(EW / 4 / 256), 256>>>(Wq, Wqs, EW);
    cvt_kernel<<<(int)(EW / 4 / 256), 256>>>(Wk, Wks, EW);
    cvt_kernel<<<(int)(EW / 4 / 256), 256>>>(Wv, Wvs, EW);
    cvt_kernel<<<(int)(EW / 4 / 256), 256>>>(Wo, Wos, EW);

    // projections: y = x @ W^T + b   (masked rows -> bias only)
    gemm_kernel<<<dim3(ND / 128, M / 128, 1), 256, GEMM_SMEM>>>(
        qs, 0, Wqs, 0, qp, qps, 0, bq, nullptr, ND, ND, 1.0f,
        qm, 0, nullptr, 0, nullptr, 0, 0);
    gemm_kernel<<<dim3(ND / 128, M / 128, 1), 256, GEMM_SMEM>>>(
        ks, 0, Wks, 0, nullptr, kps, 0, bk, nullptr, ND, ND, 1.0f,
        km, 0, nullptr, 0, nullptr, 0, 0);
    gemm_kernel<<<dim3(ND / 128, M / 128, 1), 256, GEMM_SMEM>>>(
        vs, 0, Wvs, 0, nullptr, vps, 0, bv, nullptr, ND, ND, 1.0f,
        km, 0, nullptr, 0, nullptr, 0, 0);

    // vp -> vp^T per batch
    transpose_kernel<<<dim3(ND / 32, NL / 32, NB), 256>>>(vps, vpts);

    // scores: att[b] = scale * qp[b] @ kp[b]^T  (skip all-masked q/k tiles)
    gemm_kernel<<<dim3(NL / 128, NL / 128, NB), 256, GEMM_SMEM>>>(
        qps, sQK, kps, sQK, att, nullptr, sAT, nullptr, nullptr, ND, NL, scale,
        qm, NL, km, NL, nullptr, 0, 1);

    // masked softmax -> single fp16 att
    softmax_kernel<<<dim3(NL, NB), 256>>>(att, atts, km, qm);

    // context: ao[b] = att[b] @ vp[b]  (skip masked q tiles + masked k chunks)
    gemm_kernel<<<dim3(ND / 128, NL / 128, NB), 256, GEMM_SMEM>>>(
        atts, sAT, vpts, sQK, nullptr, aos, sQK, nullptr, nullptr, NL, ND, 1.0f,
        qm, NL, nullptr, 0, km, NL, 0);

    // output projection + bias + residual (projected q)
    gemm_kernel<<<dim3(ND / 128, M / 128, 1), 256, GEMM_SMEM>>>(
        aos, 0, Wos, 0, x, nullptr, 0, bo, qp, ND, ND, 1.0f,
        qm, 0, nullptr, 0, nullptr, 0, 0);

    // LayerNorm -> final output
    layernorm_kernel<<<M, 256>>>(x, out);
}

// round 10
// speedup vs baseline: 2.3556x; 1.0709x over previous
#include <cuda_runtime.h>
#include <cuda_fp16.h>
#include <math_constants.h>
#include <cstdint>

#define NB 8
#define NL 2048
#define ND 1024

typedef __half fp16;

// ------------------------------ scratch ------------------------------------
__device__ fp16  g_qs[NB * NL * ND], g_ks[NB * NL * ND], g_vs[NB * NL * ND];
__device__ fp16  g_Wqs[ND * ND], g_Wks[ND * ND], g_Wvs[ND * ND], g_Wos[ND * ND];
__device__ float g_qp[NB * NL * ND];
__device__ fp16  g_qps[NB * NL * ND];
__device__ fp16  g_kps[NB * NL * ND];
__device__ fp16  g_vpts[NB * NL * ND];          // v-projection, pre-transposed
__device__ fp16  g_att16[(size_t)NB * NL * NL]; // raw logits (fp16)
__device__ fp16  g_atts[(size_t)NB * NL * NL];  // softmax(att) (fp16)
__device__ fp16  g_aos[NB * NL * ND];
__device__ float g_x[NB * NL * ND];
__device__ unsigned char g_kmask[NB * NL];
__device__ unsigned char g_qmask[NB * NL];

// ------------------------------ helpers ------------------------------------
__device__ __forceinline__ uint32_t smem_u32(const void* p) {
    uint32_t a;
    asm("{ .reg .u64 t; cvta.to.shared.u64 t, %1; cvt.u32.u64 %0, t; }"
        : "=r"(a) : "l"(p));
    return a;
}

__device__ __forceinline__ void cpasync16(uint32_t dst, const void* src) {
    asm volatile("cp.async.cg.shared.global [%0], [%1], 16;" :: "r"(dst), "l"(src));
}

__device__ __forceinline__ void ldsm4(uint32_t* r, uint32_t addr) {
    asm volatile("ldmatrix.sync.aligned.m8n8.x4.shared.b16 {%0,%1,%2,%3}, [%4];"
                 : "=r"(r[0]), "=r"(r[1]), "=r"(r[2]), "=r"(r[3]) : "r"(addr));
}

__device__ __forceinline__ void mma16816(float* d, const uint32_t* a, const uint32_t* b) {
    asm volatile(
        "mma.sync.aligned.m16n8k16.row.col.f32.f16.f16.f32 "
        "{%0,%1,%2,%3}, {%4,%5,%6,%7}, {%8,%9}, {%0,%1,%2,%3};"
        : "+f"(d[0]), "+f"(d[1]), "+f"(d[2]), "+f"(d[3])
        : "r"(a[0]), "r"(a[1]), "r"(a[2]), "r"(a[3]), "r"(b[0]), "r"(b[1]));
}

// ------------------------------ GEMM ---------------------------------------
// C[M,N] = alpha * A[M,K] @ B[N,K]^T   (single fp16 operands, fp32 accum)
// CTA tile 128x128, BK=128 (256B rows), 8 warps (2x4), warp tile 64x32.
// 2-stage cp.async pipeline, 64KB/stage. Mask-aware tile/chunk skipping.
// Output paths: Cf (fp32), Cs (fp16), Ct (fp16 transposed per-batch [N][L]).
#define STG_A   0u
#define STG_B   32768u
#define STG_BYTES 65536u
#define GEMM_SMEM (2u * STG_BYTES)
#define MAXCH 16

__device__ __forceinline__ void load_stage(
    const fp16* __restrict__ A, const fp16* __restrict__ B,
    int K, long long m0, long long n0, long long kb, uint32_t sb, int tid) {
#pragma unroll
    for (int i = 0; i < 8; i++) {
        int idx = tid + i * 256;              // 0..2047: 128 rows x 16 chunks
        int row = idx >> 4, ch = idx & 15;
        uint32_t sw = (uint32_t)(row * 256 + ((ch ^ (row & 7)) << 4));
        cpasync16(sb + STG_A + sw, A + (m0 + row) * K + kb + ch * 8);
        cpasync16(sb + STG_B + sw, B + (n0 + row) * K + kb + ch * 8);
    }
    asm volatile("cp.async.commit_group;" ::: "memory");
}

__global__ __launch_bounds__(256, 1)
void gemm_kernel(const fp16* __restrict__ A, long long sA,
                 const fp16* __restrict__ B, long long sB,
                 float* __restrict__ Cf, fp16* __restrict__ Cs,
                 fp16* __restrict__ Ct, long long sC,
                 const float* __restrict__ bias, const float* __restrict__ res,
                 int K, int ldC, float alpha,
                 const unsigned char* __restrict__ mM, long long mMs,
                 const unsigned char* __restrict__ mN, long long mNs,
                 const unsigned char* __restrict__ mK, long long mKs,
                 int skipM) {
    extern __shared__ char dsm[];
    const uint32_t sb0 = smem_u32(dsm);
    const int tid = threadIdx.x;
    const int lane = tid & 31, wid = tid >> 5;
    const int warp_m = wid >> 2, warp_n = wid & 3;
    const int bz = blockIdx.z;
    A += (long long)bz * sA;
    B += (long long)bz * sB;
    const long long coff = (long long)bz * sC;
    const long long m0 = (long long)blockIdx.y * 128;
    const long long n0 = (long long)blockIdx.x * 128;

    // ---------------- mask checks (uniform across CTA) --------------------
    int biasOnly = 0;
    if (mM) {
        mM += (long long)bz * mMs;
        int v = (tid < 128) ? (int)mM[m0 + tid] : 1;
        biasOnly = __syncthreads_and(v);
        if (biasOnly && skipM) return;
    }
    if (!biasOnly && mN) {
        mN += (long long)bz * mNs;
        int v = (tid < 128) ? (int)mN[n0 + tid] : 1;
        if (__syncthreads_and(v)) return;
    }

    // ---------------- active k-chunk list (chunks of 128) ------------------
    __shared__ int s_list[MAXCH];
    __shared__ int s_cnt;
    const int nchunks = K >> 7;
    if (!biasOnly) {
        if (mK) {
            mK += (long long)bz * mKs;
            __shared__ int s_flags[MAXCH];
            if (tid < nchunks) {
                const uint4* p = (const uint4*)(mK + tid * 128);
                uint32_t andall = 0xFFFFFFFFu;
#pragma unroll
                for (int j = 0; j < 8; j++) {
                    uint4 x = p[j];
                    andall &= x.x & x.y & x.z & x.w;
                }
                s_flags[tid] = (andall == 0x01010101u);
            }
            __syncthreads();
            if (tid == 0) {
                int n = 0;
                for (int c = 0; c < nchunks; c++)
                    if (!s_flags[c]) s_list[n++] = c;
                s_cnt = n;
            }
            __syncthreads();
        } else {
            if (tid < nchunks) s_list[tid] = tid;
            if (tid == 0) s_cnt = nchunks;
            __syncthreads();
        }
    }

    float acc[4][4][4];
#pragma unroll
    for (int a = 0; a < 4; a++)
#pragma unroll
        for (int b = 0; b < 4; b++)
#pragma unroll
            for (int c = 0; c < 4; c++) acc[a][b][c] = 0.0f;

    // lane-invariant fragment addressing
    const int aRow = warp_m * 64 + ((lane >> 3) & 1) * 8 + (lane & 7);
    const int aSel = lane >> 4;          // 0/1 -> 8-wide k sub-chunk
    const int bRow = warp_n * 32 + (lane >> 4) * 8 + (lane & 7);
    const int bSel = (lane >> 3) & 1;

    const int cnt = biasOnly ? 0 : s_cnt;
    if (cnt > 0) {
        load_stage(A, B, K, m0, n0, (long long)s_list[0] * 128, sb0, tid);
        for (int i = 0; i < cnt; i++) {
            const uint32_t sb = sb0 + (uint32_t)(i & 1) * STG_BYTES;
            if (i + 1 < cnt) {
                load_stage(A, B, K, m0, n0, (long long)s_list[i + 1] * 128,
                           sb0 + (uint32_t)((i + 1) & 1) * STG_BYTES, tid);
                asm volatile("cp.async.wait_group 1;" ::: "memory");
            } else {
                asm volatile("cp.async.wait_group 0;" ::: "memory");
            }
            __syncthreads();

#pragma unroll
            for (int s = 0; s < 8; s++) {
                uint32_t aa[4][4], bb[2][4];
#pragma unroll
                for (int mt = 0; mt < 4; mt++) {
                    int r = aRow + mt * 16;
                    ldsm4(aa[mt], sb + STG_A +
                          (uint32_t)(r * 256 + (((2 * s + aSel) ^ (r & 7)) << 4)));
                }
#pragma unroll
                for (int p = 0; p < 2; p++) {
                    int r = bRow + p * 16;
                    ldsm4(bb[p], sb + STG_B +
                          (uint32_t)(r * 256 + (((2 * s + bSel) ^ (r & 7)) << 4)));
                }
#pragma unroll
                for (int mt = 0; mt < 4; mt++)
#pragma unroll
                    for (int nt = 0; nt < 4; nt++)
                        mma16816(acc[mt][nt], aa[mt], &bb[nt >> 1][(nt & 1) * 2]);
            }
            __syncthreads();
        }
    }

    // ---------------- epilogue -------------------------------------------
    const int g = lane >> 2, t = lane & 3;
    fp16* Tp = (fp16*)dsm;   // transposed staging: [128 cols][136 rows]
    if (Ct) __syncthreads(); // ensure mainloop smem reads done (no-op if cnt==0)

#pragma unroll
    for (int mt = 0; mt < 4; mt++) {
#pragma unroll
        for (int nt = 0; nt < 4; nt++) {
            float* d = acc[mt][nt];
            int rloc = warp_m * 64 + mt * 16 + g;          // 0..127 within tile
            int cloc = warp_n * 32 + nt * 8 + t * 2;       // 0..126 within tile
            int row0 = (int)m0 + rloc;
            int col  = (int)n0 + cloc;
            float v0 = d[0] * alpha, v1 = d[1] * alpha;
            float v2 = d[2] * alpha, v3 = d[3] * alpha;
            if (bias) {
                float b0 = bias[col], b1 = bias[col + 1];
                v0 += b0; v1 += b1; v2 += b0; v3 += b1;
            }
            long long o0 = coff + (long long)row0 * ldC + col;
            long long o1 = o0 + 8LL * ldC;
            if (res) {
                v0 += res[o0]; v1 += res[o0 + 1];
                v2 += res[o1]; v3 += res[o1 + 1];
            }
            if (Cf) {
                *(float2*)(Cf + o0) = make_float2(v0, v1);
                *(float2*)(Cf + o1) = make_float2(v2, v3);
            }
            if (Cs) {
                *(__half2*)(Cs + o0) = __halves2half2(__float2half_rn(v0), __float2half_rn(v1));
                *(__half2*)(Cs + o1) = __halves2half2(__float2half_rn(v2), __float2half_rn(v3));
            }
            if (Ct) {
                Tp[(cloc + 0) * 136 + rloc]     = __float2half_rn(v0);
                Tp[(cloc + 1) * 136 + rloc]     = __float2half_rn(v1);
                Tp[(cloc + 0) * 136 + rloc + 8] = __float2half_rn(v2);
                Tp[(cloc + 1) * 136 + rloc + 8] = __float2half_rn(v3);
            }
        }
    }
    if (Ct) {
        __syncthreads();
        // per-batch transposed layout: Ct[b][n][l], b = m0/NL, l0 = m0%NL
        const long long b = m0 >> 11;            // NL = 2048
        const long long l0 = m0 & (NL - 1);
        fp16* base = Ct + b * (long long)ND * NL + l0;
#pragma unroll
        for (int c = wid; c < 128; c += 8) {
            uint2 val = *(uint2*)(Tp + c * 136 + lane * 4);
            *(uint2*)(base + (n0 + c) * NL + lane * 4) = val;
        }
    }
}

// ---------------- fused fp32 -> fp16 convert + row-zero mask ----------------
__global__ __launch_bounds__(256)
void cvtmask_kernel(const float* __restrict__ x, fp16* __restrict__ s,
                    unsigned char* __restrict__ m) {
    int r = blockIdx.x;
    int tid = threadIdx.x;
    float4 v = ((const float4*)(x + (long long)r * ND))[tid];

    __shared__ float red[256];
    red[tid] = (v.x + v.y) + (v.z + v.w);
    __syncthreads();
    for (int st = 128; st > 0; st >>= 1) {
        if (tid < st) red[tid] += red[tid + st];
        __syncthreads();
    }
    if (tid == 0) m[r] = (red[0] == 0.0f) ? 1 : 0;

    fp16 ss[4] = {__float2half_rn(v.x), __float2half_rn(v.y),
                  __float2half_rn(v.z), __float2half_rn(v.w)};
    *(uint2*)(s + (long long)r * ND + tid * 4) = *(uint2*)ss;
}

// ---------------- fp32 -> fp16 convert ---------------------------------------
__global__ __launch_bounds__(256)
void cvt_kernel(const float* __restrict__ x, fp16* __restrict__ s, long long n) {
    long long i = ((long long)blockIdx.x * 256 + threadIdx.x) * 4;
    if (i >= n) return;
    float4 v = *(const float4*)(x + i);
    fp16 ss[4] = {__float2half_rn(v.x), __float2half_rn(v.y),
                  __float2half_rn(v.z), __float2half_rn(v.w)};
    *(uint2*)(s + i) = *(uint2*)ss;
}

// ---------------- batched weight convert (4 tensors, one launch) -------------
__global__ __launch_bounds__(256)
void wcvt_kernel(const float* __restrict__ W0, const float* __restrict__ W1,
                 const float* __restrict__ W2, const float* __restrict__ W3,
                 fp16* __restrict__ S0, fp16* __restrict__ S1,
                 fp16* __restrict__ S2, fp16* __restrict__ S3) {
    int w = blockIdx.y;
    const float* W = (w == 0) ? W0 : (w == 1) ? W1 : (w == 2) ? W2 : W3;
    fp16* S = (w == 0) ? S0 : (w == 1) ? S1 : (w == 2) ? S2 : S3;
    long long i = ((long long)blockIdx.x * 256 + threadIdx.x) * 4;
    float4 v = *(const float4*)(W + i);
    fp16 ss[4] = {__float2half_rn(v.x), __float2half_rn(v.y),
                  __float2half_rn(v.z), __float2half_rn(v.w)};
    *(uint2*)(S + i) = *(uint2*)ss;
}

// ---------------- masked softmax (fp16 in, fp16 out) -------------------------
__global__ __launch_bounds__(256)
void softmax_kernel(const fp16* __restrict__ att, fp16* __restrict__ atts,
                    const unsigned char* __restrict__ km,
                    const unsigned char* __restrict__ qm) {
    int i = blockIdx.x;
    int b = blockIdx.y;
    int tid = threadIdx.x;
    const fp16* row = att + ((long long)b * NL + i) * NL;
    fp16* os = atts + ((long long)b * NL + i) * NL;
    const unsigned char* kmb = km + b * NL;
    bool qz = qm[b * NL + i] != 0;

    if (qz) {   // masked q row: output exactly zero, never read scores
        ((uint4*)os)[tid * 2]     = make_uint4(0, 0, 0, 0);
        ((uint4*)os)[tid * 2 + 1] = make_uint4(0, 0, 0, 0);
        return;
    }

    float vals[NL / 256];
    float mx = -CUDART_INF_F;
#pragma unroll
    for (int t = 0; t < NL / 256; t++) {
        int j = tid + t * 256;
        float v = kmb[j] ? -CUDART_INF_F : __half2float(row[j]);
        vals[t] = v;
        mx = fmaxf(mx, v);
    }
    __shared__ float red[256];
    red[tid] = mx;
    __syncthreads();
    for (int s = 128; s > 0; s >>= 1) {
        if (tid < s) red[tid] = fmaxf(red[tid], red[tid + s]);
        __syncthreads();
    }
    mx = red[0];
    __syncthreads();

    float sum = 0.f;
#pragma unroll
    for (int t = 0; t < NL / 256; t++) {
        float e = __expf(vals[t] - mx);
        vals[t] = e;
        sum += e;
    }
    red[tid] = sum;
    __syncthreads();
    for (int s = 128; s > 0; s >>= 1) {
        if (tid < s) red[tid] += red[tid + s];
        __syncthreads();
    }
    float inv = 1.0f / red[0];
#pragma unroll
    for (int t = 0; t < NL / 256; t++) {
        int j = tid + t * 256;
        os[j] = __float2half_rn(vals[t] * inv);
    }
}

// ---------------- LayerNorm (no affine), row length 1024 --------------------
__global__ __launch_bounds__(256)
void layernorm_kernel(const float* __restrict__ x, float* __restrict__ out) {
    int r = blockIdx.x;
    int tid = threadIdx.x;
    const float4* xr = (const float4*)(x + (long long)r * ND);
    float4 v = xr[tid];
    __shared__ float red[256];

    red[tid] = (v.x + v.y) + (v.z + v.w);
    __syncthreads();
    for (int s = 128; s > 0; s >>= 1) {
        if (tid < s) red[tid] += red[tid + s];
        __syncthreads();
    }
    float mu = red[0] * (1.0f / ND);
    __syncthreads();

    float dx = v.x - mu, dy = v.y - mu, dz = v.z - mu, dw = v.w - mu;
    red[tid] = dx * dx + dy * dy + dz * dz + dw * dw;
    __syncthreads();
    for (int s = 128; s > 0; s >>= 1) {
        if (tid < s) red[tid] += red[tid + s];
        __syncthreads();
    }
    float inv = rsqrtf(red[0] * (1.0f / ND) + 1e-5f);

    float4 o;
    o.x = dx * inv; o.y = dy * inv; o.z = dz * inv; o.w = dw * inv;
    ((float4*)(out + (long long)r * ND))[tid] = o;
}

// ---------------- launch -----------------------------------------------------
extern "C" void kernel_launch(void* const* d_in, const int* in_sizes, int n_in,
                              void* d_out, int out_size) {
    const float* q  = (const float*)d_in[0];
    const float* k  = (const float*)d_in[1];
    const float* v  = (const float*)d_in[2];
    const float* Wq = (const float*)d_in[3];
    const float* bq = (const float*)d_in[4];
    const float* Wk = (const float*)d_in[5];
    const float* bk = (const float*)d_in[6];
    const float* Wv = (const float*)d_in[7];
    const float* bv = (const float*)d_in[8];
    const float* Wo = (const float*)d_in[9];
    const float* bo = (const float*)d_in[10];
    float* out = (float*)d_out;

    fp16 *qs, *ks, *vs, *Wqs, *Wks, *Wvs, *Wos;
    float *qp, *x;
    fp16 *qps, *kps, *vpts, *att16, *atts, *aos;
    unsigned char *km, *qm;
    cudaGetSymbolAddress((void**)&qs,  g_qs);
    cudaGetSymbolAddress((void**)&ks,  g_ks);
    cudaGetSymbolAddress((void**)&vs,  g_vs);
    cudaGetSymbolAddress((void**)&Wqs, g_Wqs);  cudaGetSymbolAddress((void**)&Wks, g_Wks);
    cudaGetSymbolAddress((void**)&Wvs, g_Wvs);  cudaGetSymbolAddress((void**)&Wos, g_Wos);
    cudaGetSymbolAddress((void**)&qp,  g_qp);
    cudaGetSymbolAddress((void**)&qps, g_qps);
    cudaGetSymbolAddress((void**)&kps, g_kps);
    cudaGetSymbolAddress((void**)&vpts, g_vpts);
    cudaGetSymbolAddress((void**)&att16, g_att16);
    cudaGetSymbolAddress((void**)&atts, g_atts);
    cudaGetSymbolAddress((void**)&aos, g_aos);
    cudaGetSymbolAddress((void**)&x,   g_x);
    cudaGetSymbolAddress((void**)&km,  g_kmask); cudaGetSymbolAddress((void**)&qm, g_qmask);

    cudaFuncSetAttribute(gemm_kernel, cudaFuncAttributeMaxDynamicSharedMemorySize, GEMM_SMEM);

    const long long E  = (long long)NB * NL * ND;
    const long long EW = (long long)ND * ND;
    const int M = NB * NL;
    const long long sQK = (long long)NL * ND;
    const long long sAT = (long long)NL * NL;
    const float scale = 0.03125f;

    // converts + masks
    cvtmask_kernel<<<M, 256>>>(q, qs, qm);
    cvtmask_kernel<<<M, 256>>>(k, ks, km);
    cvt_kernel<<<(int)(E / 4 / 256), 256>>>(v, vs, E);
    wcvt_kernel<<<dim3((int)(EW / 4 / 256), 4), 256>>>(
        Wq, Wk, Wv, Wo, Wqs, Wks, Wvs, Wos);

    // projections: y = x @ W^T + b   (masked rows -> bias only)
    gemm_kernel<<<dim3(ND / 128, M / 128, 1), 256, GEMM_SMEM>>>(
        qs, 0, Wqs, 0, qp, qps, nullptr, 0, bq, nullptr, ND, ND, 1.0f,
        qm, 0, nullptr, 0, nullptr, 0, 0);
    gemm_kernel<<<dim3(ND / 128, M / 128, 1), 256, GEMM_SMEM>>>(
        ks, 0, Wks, 0, nullptr, kps, nullptr, 0, bk, nullptr, ND, ND, 1.0f,
        km, 0, nullptr, 0, nullptr, 0, 0);
    // v projection writes TRANSPOSED output directly (per-batch [ND][NL])
    gemm_kernel<<<dim3(ND / 128, M / 128, 1), 256, GEMM_SMEM>>>(
        vs, 0, Wvs, 0, nullptr, nullptr, vpts, 0, bv, nullptr, ND, ND, 1.0f,
        km, 0, nullptr, 0, nullptr, 0, 0);

    // scores: att16[b] = scale * qp[b] @ kp[b]^T  (fp16 logits, skip masked tiles)
    gemm_kernel<<<dim3(NL / 128, NL / 128, NB), 256, GEMM_SMEM>>>(
        qps, sQK, kps, sQK, nullptr, att16, nullptr, sAT, nullptr, nullptr,
        ND, NL, scale,
        qm, NL, km, NL, nullptr, 0, 1);

    // masked softmax (fp16 -> fp16)
    softmax_kernel<<<dim3(NL, NB), 256>>>(att16, atts, km, qm);

    // context: ao[b] = att[b] @ vp[b]  (skip masked q tiles + masked k chunks)
    gemm_kernel<<<dim3(ND / 128, NL / 128, NB), 256, GEMM_SMEM>>>(
        atts, sAT, vpts, sQK, nullptr, aos, nullptr, sQK, nullptr, nullptr,
        NL, ND, 1.0f,
        qm, NL, nullptr, 0, km, NL, 0);

    // output projection + bias + residual (projected q)
    gemm_kernel<<<dim3(ND / 128, M / 128, 1), 256, GEMM_SMEM>>>(
        aos, 0, Wos, 0, x, nullptr, nullptr, 0, bo, qp, ND, ND, 1.0f,
        qm, 0, nullptr, 0, nullptr, 0, 0);

    // LayerNorm -> final output
    layernorm_kernel<<<M, 256>>>(x, out);
}

// round 11
// speedup vs baseline: 2.6273x; 1.1154x over previous
#include <cuda_runtime.h>
#include <cuda_fp16.h>
#include <math_constants.h>
#include <cstdint>

#define NB 8
#define NL 2048
#define ND 1024

typedef __half fp16;

// ------------------------------ scratch ------------------------------------
__device__ fp16  g_qs[NB * NL * ND], g_ks[NB * NL * ND], g_vs[NB * NL * ND];
__device__ fp16  g_Wqs[ND * ND], g_Wks[ND * ND], g_Wvs[ND * ND], g_Wos[ND * ND];
__device__ float g_qp[NB * NL * ND];
__device__ fp16  g_qps[NB * NL * ND];
__device__ fp16  g_kps[NB * NL * ND];
__device__ fp16  g_vpts[NB * NL * ND];          // v-projection, pre-transposed
__device__ fp16  g_att16[(size_t)NB * NL * NL]; // raw logits (fp16)
__device__ fp16  g_atts[(size_t)NB * NL * NL];  // softmax(att) (fp16)
__device__ fp16  g_aos[NB * NL * ND];
__device__ float g_x[NB * NL * ND];
__device__ unsigned char g_kmask[NB * NL];
__device__ unsigned char g_qmask[NB * NL];

// ------------------------------ helpers ------------------------------------
__device__ __forceinline__ uint32_t smem_u32(const void* p) {
    uint32_t a;
    asm("{ .reg .u64 t; cvta.to.shared.u64 t, %1; cvt.u32.u64 %0, t; }"
        : "=r"(a) : "l"(p));
    return a;
}

__device__ __forceinline__ void cpasync16(uint32_t dst, const void* src) {
    asm volatile("cp.async.cg.shared.global [%0], [%1], 16;" :: "r"(dst), "l"(src));
}

__device__ __forceinline__ void ldsm4(uint32_t* r, uint32_t addr) {
    asm volatile("ldmatrix.sync.aligned.m8n8.x4.shared.b16 {%0,%1,%2,%3}, [%4];"
                 : "=r"(r[0]), "=r"(r[1]), "=r"(r[2]), "=r"(r[3]) : "r"(addr));
}

__device__ __forceinline__ void mma16816(float* d, const uint32_t* a, const uint32_t* b) {
    asm volatile(
        "mma.sync.aligned.m16n8k16.row.col.f32.f16.f16.f32 "
        "{%0,%1,%2,%3}, {%4,%5,%6,%7}, {%8,%9}, {%0,%1,%2,%3};"
        : "+f"(d[0]), "+f"(d[1]), "+f"(d[2]), "+f"(d[3])
        : "r"(a[0]), "r"(a[1]), "r"(a[2]), "r"(a[3]), "r"(b[0]), "r"(b[1]));
}

// ------------------------------ GEMM ---------------------------------------
// C[M,N] = alpha * A[M,K] @ B[N,K]^T   (single fp16 operands, fp32 accum)
// CTA tile 256x128, BK=128 (256B rows), 8 warps (4x2), warp tile 64x64.
// 2-stage cp.async pipeline, 96KB/stage. Mask-aware tile/chunk skipping.
// Output paths: Cf (fp32), Cs (fp16), Ct (fp16 transposed per-batch [N][L]).
#define BM 256
#define STG_A   0u
#define STG_B   65536u
#define STG_BYTES 98304u
#define GEMM_SMEM (2u * STG_BYTES)
#define MAXCH 16

__device__ __forceinline__ void load_stage(
    const fp16* __restrict__ A, const fp16* __restrict__ B,
    int K, long long m0, long long n0, long long kb, uint32_t sb, int tid) {
#pragma unroll
    for (int i = 0; i < 16; i++) {            // A: 256 rows x 16 chunks
        int idx = tid + i * 256;
        int row = idx >> 4, ch = idx & 15;
        uint32_t sw = (uint32_t)(row * 256 + ((ch ^ (row & 7)) << 4));
        cpasync16(sb + STG_A + sw, A + (m0 + row) * K + kb + ch * 8);
    }
#pragma unroll
    for (int i = 0; i < 8; i++) {             // B: 128 rows x 16 chunks
        int idx = tid + i * 256;
        int row = idx >> 4, ch = idx & 15;
        uint32_t sw = (uint32_t)(row * 256 + ((ch ^ (row & 7)) << 4));
        cpasync16(sb + STG_B + sw, B + (n0 + row) * K + kb + ch * 8);
    }
    asm volatile("cp.async.commit_group;" ::: "memory");
}

__global__ __launch_bounds__(256, 1)
void gemm_kernel(const fp16* __restrict__ A, long long sA,
                 const fp16* __restrict__ B, long long sB,
                 float* __restrict__ Cf, fp16* __restrict__ Cs,
                 fp16* __restrict__ Ct, long long sC,
                 const float* __restrict__ bias, const float* __restrict__ res,
                 int K, int ldC, float alpha,
                 const unsigned char* __restrict__ mM, long long mMs,
                 const unsigned char* __restrict__ mN, long long mNs,
                 const unsigned char* __restrict__ mK, long long mKs,
                 int skipM) {
    extern __shared__ char dsm[];
    const uint32_t sb0 = smem_u32(dsm);
    const int tid = threadIdx.x;
    const int lane = tid & 31, wid = tid >> 5;
    const int warp_m = wid >> 1, warp_n = wid & 1;   // 4 x 2 warp grid
    const int bz = blockIdx.z;
    A += (long long)bz * sA;
    B += (long long)bz * sB;
    const long long coff = (long long)bz * sC;
    const long long m0 = (long long)blockIdx.y * BM;
    const long long n0 = (long long)blockIdx.x * 128;

    // ---------------- mask checks (uniform across CTA) --------------------
    int biasOnly = 0;
    if (mM) {
        mM += (long long)bz * mMs;
        int v = (int)mM[m0 + tid];                 // 256 threads, 256 rows
        biasOnly = __syncthreads_and(v);
        if (biasOnly && skipM) return;
    }
    if (!biasOnly && mN) {
        mN += (long long)bz * mNs;
        int v = (tid < 128) ? (int)mN[n0 + tid] : 1;
        if (__syncthreads_and(v)) return;
    }

    // ---------------- active k-chunk list (chunks of 128) ------------------
    __shared__ int s_list[MAXCH];
    __shared__ int s_cnt;
    const int nchunks = K >> 7;
    if (!biasOnly) {
        if (mK) {
            mK += (long long)bz * mKs;
            __shared__ int s_flags[MAXCH];
            if (tid < nchunks) {
                const uint4* p = (const uint4*)(mK + tid * 128);
                uint32_t andall = 0xFFFFFFFFu;
#pragma unroll
                for (int j = 0; j < 8; j++) {
                    uint4 x = p[j];
                    andall &= x.x & x.y & x.z & x.w;
                }
                s_flags[tid] = (andall == 0x01010101u);
            }
            __syncthreads();
            if (tid == 0) {
                int n = 0;
                for (int c = 0; c < nchunks; c++)
                    if (!s_flags[c]) s_list[n++] = c;
                s_cnt = n;
            }
            __syncthreads();
        } else {
            if (tid < nchunks) s_list[tid] = tid;
            if (tid == 0) s_cnt = nchunks;
            __syncthreads();
        }
    }

    float acc[4][8][4];
#pragma unroll
    for (int a = 0; a < 4; a++)
#pragma unroll
        for (int b = 0; b < 8; b++)
#pragma unroll
            for (int c = 0; c < 4; c++) acc[a][b][c] = 0.0f;

    // lane-invariant fragment addressing
    const int aRow = warp_m * 64 + ((lane >> 3) & 1) * 8 + (lane & 7);
    const int aSel = lane >> 4;          // 0/1 -> 8-wide k sub-chunk
    const int bRow = warp_n * 64 + (lane >> 4) * 8 + (lane & 7);
    const int bSel = (lane >> 3) & 1;

    const int cnt = biasOnly ? 0 : s_cnt;
    if (cnt > 0) {
        load_stage(A, B, K, m0, n0, (long long)s_list[0] * 128, sb0, tid);
        for (int i = 0; i < cnt; i++) {
            const uint32_t sb = sb0 + (uint32_t)(i & 1) * STG_BYTES;
            if (i + 1 < cnt) {
                load_stage(A, B, K, m0, n0, (long long)s_list[i + 1] * 128,
                           sb0 + (uint32_t)((i + 1) & 1) * STG_BYTES, tid);
                asm volatile("cp.async.wait_group 1;" ::: "memory");
            } else {
                asm volatile("cp.async.wait_group 0;" ::: "memory");
            }
            __syncthreads();

#pragma unroll
            for (int s = 0; s < 8; s++) {
                uint32_t aa[4][4], bb[4][4];
#pragma unroll
                for (int mt = 0; mt < 4; mt++) {
                    int r = aRow + mt * 16;
                    ldsm4(aa[mt], sb + STG_A +
                          (uint32_t)(r * 256 + (((2 * s + aSel) ^ (r & 7)) << 4)));
                }
#pragma unroll
                for (int p = 0; p < 4; p++) {
                    int r = bRow + p * 16;
                    ldsm4(bb[p], sb + STG_B +
                          (uint32_t)(r * 256 + (((2 * s + bSel) ^ (r & 7)) << 4)));
                }
#pragma unroll
                for (int mt = 0; mt < 4; mt++)
#pragma unroll
                    for (int nt = 0; nt < 8; nt++)
                        mma16816(acc[mt][nt], aa[mt], &bb[nt >> 1][(nt & 1) * 2]);
            }
            __syncthreads();
        }
    }

    // ---------------- epilogue -------------------------------------------
    const int g = lane >> 2, t = lane & 3;
    fp16* Tp = (fp16*)dsm;   // transposed staging: [128 cols][264 row-stride]
    if (Ct) __syncthreads();

#pragma unroll
    for (int mt = 0; mt < 4; mt++) {
#pragma unroll
        for (int nt = 0; nt < 8; nt++) {
            float* d = acc[mt][nt];
            int rloc = warp_m * 64 + mt * 16 + g;          // 0..255 within tile
            int cloc = warp_n * 64 + nt * 8 + t * 2;       // 0..126 within tile
            int row0 = (int)m0 + rloc;
            int col  = (int)n0 + cloc;
            float v0 = d[0] * alpha, v1 = d[1] * alpha;
            float v2 = d[2] * alpha, v3 = d[3] * alpha;
            if (bias) {
                float b0 = bias[col], b1 = bias[col + 1];
                v0 += b0; v1 += b1; v2 += b0; v3 += b1;
            }
            long long o0 = coff + (long long)row0 * ldC + col;
            long long o1 = o0 + 8LL * ldC;
            if (res) {
                v0 += res[o0]; v1 += res[o0 + 1];
                v2 += res[o1]; v3 += res[o1 + 1];
            }
            if (Cf) {
                *(float2*)(Cf + o0) = make_float2(v0, v1);
                *(float2*)(Cf + o1) = make_float2(v2, v3);
            }
            if (Cs) {
                *(__half2*)(Cs + o0) = __halves2half2(__float2half_rn(v0), __float2half_rn(v1));
                *(__half2*)(Cs + o1) = __halves2half2(__float2half_rn(v2), __float2half_rn(v3));
            }
            if (Ct) {
                Tp[(cloc + 0) * 264 + rloc]     = __float2half_rn(v0);
                Tp[(cloc + 1) * 264 + rloc]     = __float2half_rn(v1);
                Tp[(cloc + 0) * 264 + rloc + 8] = __float2half_rn(v2);
                Tp[(cloc + 1) * 264 + rloc + 8] = __float2half_rn(v3);
            }
        }
    }
    if (Ct) {
        __syncthreads();
        // per-batch transposed layout: Ct[b][n][l], b = m0/NL, l0 = m0%NL
        const long long b = m0 >> 11;            // NL = 2048
        const long long l0 = m0 & (NL - 1);
        fp16* base = Ct + b * (long long)ND * NL + l0;
#pragma unroll
        for (int c = wid; c < 128; c += 8) {
            uint2 v0 = *(uint2*)(Tp + c * 264 + lane * 4);
            uint2 v1 = *(uint2*)(Tp + c * 264 + 128 + lane * 4);
            *(uint2*)(base + (n0 + c) * NL + lane * 4) = v0;
            *(uint2*)(base + (n0 + c) * NL + 128 + lane * 4) = v1;
        }
    }
}

// ---------------- fused fp32 -> fp16 convert + row-zero mask ----------------
__global__ __launch_bounds__(256)
void cvtmask_kernel(const float* __restrict__ x, fp16* __restrict__ s,
                    unsigned char* __restrict__ m) {
    int r = blockIdx.x;
    int tid = threadIdx.x;
    float4 v = ((const float4*)(x + (long long)r * ND))[tid];

    __shared__ float red[256];
    red[tid] = (v.x + v.y) + (v.z + v.w);
    __syncthreads();
    for (int st = 128; st > 0; st >>= 1) {
        if (tid < st) red[tid] += red[tid + st];
        __syncthreads();
    }
    if (tid == 0) m[r] = (red[0] == 0.0f) ? 1 : 0;

    fp16 ss[4] = {__float2half_rn(v.x), __float2half_rn(v.y),
                  __float2half_rn(v.z), __float2half_rn(v.w)};
    *(uint2*)(s + (long long)r * ND + tid * 4) = *(uint2*)ss;
}

// ---------------- fp32 -> fp16 convert ---------------------------------------
__global__ __launch_bounds__(256)
void cvt_kernel(const float* __restrict__ x, fp16* __restrict__ s, long long n) {
    long long i = ((long long)blockIdx.x * 256 + threadIdx.x) * 4;
    if (i >= n) return;
    float4 v = *(const float4*)(x + i);
    fp16 ss[4] = {__float2half_rn(v.x), __float2half_rn(v.y),
                  __float2half_rn(v.z), __float2half_rn(v.w)};
    *(uint2*)(s + i) = *(uint2*)ss;
}

// ---------------- batched weight convert (4 tensors, one launch) -------------
__global__ __launch_bounds__(256)
void wcvt_kernel(const float* __restrict__ W0, const float* __restrict__ W1,
                 const float* __restrict__ W2, const float* __restrict__ W3,
                 fp16* __restrict__ S0, fp16* __restrict__ S1,
                 fp16* __restrict__ S2, fp16* __restrict__ S3) {
    int w = blockIdx.y;
    const float* W = (w == 0) ? W0 : (w == 1) ? W1 : (w == 2) ? W2 : W3;
    fp16* S = (w == 0) ? S0 : (w == 1) ? S1 : (w == 2) ? S2 : S3;
    long long i = ((long long)blockIdx.x * 256 + threadIdx.x) * 4;
    float4 v = *(const float4*)(W + i);
    fp16 ss[4] = {__float2half_rn(v.x), __float2half_rn(v.y),
                  __float2half_rn(v.z), __float2half_rn(v.w)};
    *(uint2*)(S + i) = *(uint2*)ss;
}

// ---------------- masked softmax (fp16 in, fp16 out) -------------------------
__global__ __launch_bounds__(256)
void softmax_kernel(const fp16* __restrict__ att, fp16* __restrict__ atts,
                    const unsigned char* __restrict__ km,
                    const unsigned char* __restrict__ qm) {
    int i = blockIdx.x;
    int b = blockIdx.y;
    int tid = threadIdx.x;
    const fp16* row = att + ((long long)b * NL + i) * NL;
    fp16* os = atts + ((long long)b * NL + i) * NL;
    const unsigned char* kmb = km + b * NL;
    bool qz = qm[b * NL + i] != 0;

    if (qz) {   // masked q row: output exactly zero, never read scores
        ((uint4*)os)[tid * 2]     = make_uint4(0, 0, 0, 0);
        ((uint4*)os)[tid * 2 + 1] = make_uint4(0, 0, 0, 0);
        return;
    }

    float vals[NL / 256];
    float mx = -CUDART_INF_F;
#pragma unroll
    for (int t = 0; t < NL / 256; t++) {
        int j = tid + t * 256;
        float v = kmb[j] ? -CUDART_INF_F : __half2float(row[j]);
        vals[t] = v;
        mx = fmaxf(mx, v);
    }
    __shared__ float red[256];
    red[tid] = mx;
    __syncthreads();
    for (int s = 128; s > 0; s >>= 1) {
        if (tid < s) red[tid] = fmaxf(red[tid], red[tid + s]);
        __syncthreads();
    }
    mx = red[0];
    __syncthreads();

    float sum = 0.f;
#pragma unroll
    for (int t = 0; t < NL / 256; t++) {
        float e = __expf(vals[t] - mx);
        vals[t] = e;
        sum += e;
    }
    red[tid] = sum;
    __syncthreads();
    for (int s = 128; s > 0; s >>= 1) {
        if (tid < s) red[tid] += red[tid + s];
        __syncthreads();
    }
    float inv = 1.0f / red[0];
#pragma unroll
    for (int t = 0; t < NL / 256; t++) {
        int j = tid + t * 256;
        os[j] = __float2half_rn(vals[t] * inv);
    }
}

// ---------------- LayerNorm (no affine), row length 1024 --------------------
__global__ __launch_bounds__(256)
void layernorm_kernel(const float* __restrict__ x, float* __restrict__ out) {
    int r = blockIdx.x;
    int tid = threadIdx.x;
    const float4* xr = (const float4*)(x + (long long)r * ND);
    float4 v = xr[tid];
    __shared__ float red[256];

    red[tid] = (v.x + v.y) + (v.z + v.w);
    __syncthreads();
    for (int s = 128; s > 0; s >>= 1) {
        if (tid < s) red[tid] += red[tid + s];
        __syncthreads();
    }
    float mu = red[0] * (1.0f / ND);
    __syncthreads();

    float dx = v.x - mu, dy = v.y - mu, dz = v.z - mu, dw = v.w - mu;
    red[tid] = dx * dx + dy * dy + dz * dz + dw * dw;
    __syncthreads();
    for (int s = 128; s > 0; s >>= 1) {
        if (tid < s) red[tid] += red[tid + s];
        __syncthreads();
    }
    float inv = rsqrtf(red[0] * (1.0f / ND) + 1e-5f);

    float4 o;
    o.x = dx * inv; o.y = dy * inv; o.z = dz * inv; o.w = dw * inv;
    ((float4*)(out + (long long)r * ND))[tid] = o;
}

// ---------------- launch -----------------------------------------------------
extern "C" void kernel_launch(void* const* d_in, const int* in_sizes, int n_in,
                              void* d_out, int out_size) {
    const float* q  = (const float*)d_in[0];
    const float* k  = (const float*)d_in[1];
    const float* v  = (const float*)d_in[2];
    const float* Wq = (const float*)d_in[3];
    const float* bq = (const float*)d_in[4];
    const float* Wk = (const float*)d_in[5];
    const float* bk = (const float*)d_in[6];
    const float* Wv = (const float*)d_in[7];
    const float* bv = (const float*)d_in[8];
    const float* Wo = (const float*)d_in[9];
    const float* bo = (const float*)d_in[10];
    float* out = (float*)d_out;

    fp16 *qs, *ks, *vs, *Wqs, *Wks, *Wvs, *Wos;
    float *qp, *x;
    fp16 *qps, *kps, *vpts, *att16, *atts, *aos;
    unsigned char *km, *qm;
    cudaGetSymbolAddress((void**)&qs,  g_qs);
    cudaGetSymbolAddress((void**)&ks,  g_ks);
    cudaGetSymbolAddress((void**)&vs,  g_vs);
    cudaGetSymbolAddress((void**)&Wqs, g_Wqs);  cudaGetSymbolAddress((void**)&Wks, g_Wks);
    cudaGetSymbolAddress((void**)&Wvs, g_Wvs);  cudaGetSymbolAddress((void**)&Wos, g_Wos);
    cudaGetSymbolAddress((void**)&qp,  g_qp);
    cudaGetSymbolAddress((void**)&qps, g_qps);
    cudaGetSymbolAddress((void**)&kps, g_kps);
    cudaGetSymbolAddress((void**)&vpts, g_vpts);
    cudaGetSymbolAddress((void**)&att16, g_att16);
    cudaGetSymbolAddress((void**)&atts, g_atts);
    cudaGetSymbolAddress((void**)&aos, g_aos);
    cudaGetSymbolAddress((void**)&x,   g_x);
    cudaGetSymbolAddress((void**)&km,  g_kmask); cudaGetSymbolAddress((void**)&qm, g_qmask);

    cudaFuncSetAttribute(gemm_kernel, cudaFuncAttributeMaxDynamicSharedMemorySize, GEMM_SMEM);

    const long long E  = (long long)NB * NL * ND;
    const long long EW = (long long)ND * ND;
    const int M = NB * NL;
    const long long sQK = (long long)NL * ND;
    const long long sAT = (long long)NL * NL;
    const float scale = 0.03125f;

    // converts + masks
    cvtmask_kernel<<<M, 256>>>(q, qs, qm);
    cvtmask_kernel<<<M, 256>>>(k, ks, km);
    cvt_kernel<<<(int)(E / 4 / 256), 256>>>(v, vs, E);
    wcvt_kernel<<<dim3((int)(EW / 4 / 256), 4), 256>>>(
        Wq, Wk, Wv, Wo, Wqs, Wks, Wvs, Wos);

    // projections: y = x @ W^T + b   (masked rows -> bias only)
    gemm_kernel<<<dim3(ND / 128, M / BM, 1), 256, GEMM_SMEM>>>(
        qs, 0, Wqs, 0, qp, qps, nullptr, 0, bq, nullptr, ND, ND, 1.0f,
        qm, 0, nullptr, 0, nullptr, 0, 0);
    gemm_kernel<<<dim3(ND / 128, M / BM, 1), 256, GEMM_SMEM>>>(
        ks, 0, Wks, 0, nullptr, kps, nullptr, 0, bk, nullptr, ND, ND, 1.0f,
        km, 0, nullptr, 0, nullptr, 0, 0);
    // v projection writes TRANSPOSED output directly (per-batch [ND][NL])
    gemm_kernel<<<dim3(ND / 128, M / BM, 1), 256, GEMM_SMEM>>>(
        vs, 0, Wvs, 0, nullptr, nullptr, vpts, 0, bv, nullptr, ND, ND, 1.0f,
        km, 0, nullptr, 0, nullptr, 0, 0);

    // scores: att16[b] = scale * qp[b] @ kp[b]^T  (fp16 logits, skip masked tiles)
    gemm_kernel<<<dim3(NL / 128, NL / BM, NB), 256, GEMM_SMEM>>>(
        qps, sQK, kps, sQK, nullptr, att16, nullptr, sAT, nullptr, nullptr,
        ND, NL, scale,
        qm, NL, km, NL, nullptr, 0, 1);

    // masked softmax (fp16 -> fp16)
    softmax_kernel<<<dim3(NL, NB), 256>>>(att16, atts, km, qm);

    // context: ao[b] = att[b] @ vp[b]  (skip masked q tiles + masked k chunks)
    gemm_kernel<<<dim3(ND / 128, NL / BM, NB), 256, GEMM_SMEM>>>(
        atts, sAT, vpts, sQK, nullptr, aos, nullptr, sQK, nullptr, nullptr,
        NL, ND, 1.0f,
        qm, NL, nullptr, 0, km, NL, 0);

    // output projection + bias + residual (projected q)
    gemm_kernel<<<dim3(ND / 128, M / BM, 1), 256, GEMM_SMEM>>>(
        aos, 0, Wos, 0, x, nullptr, nullptr, 0, bo, qp, ND, ND, 1.0f,
        qm, 0, nullptr, 0, nullptr, 0, 0);

    // LayerNorm -> final output
    layernorm_kernel<<<M, 256>>>(x, out);
}